// round 12
// baseline (speedup 1.0000x reference)
#include <cuda_runtime.h>
#include <math.h>

#define G 296
#define T 256

// ---------------- device scratch ------------------------------------------
__device__ float g_nodes[256 * 128];
__device__ float g_xn   [256 * 128];
__device__ float g_q  [2][256 * 512];
__device__ float g_kT [2][1024 * 128];   // [p][b*512+c][j]
__device__ float g_v  [2][256 * 512];
__device__ float g_attp[256 * 1024];     // per-head Wo partials [row][h][128]
__device__ float g_edges[2 * 128 * 128 * 3];
__device__ float g_part [128];

// dataflow flags — each padded to its own 128B line (index * 32)
__device__ volatile int f_rt [8  * 32];
__device__ volatile int f_qkv[48 * 32];
__device__ volatile int f_att[32 * 32];
__device__ volatile int f_ez [32];
__device__ volatile int f_edge[32];
__device__ int          f_done[32];

__device__ __forceinline__ float warpsum(float v) {
#pragma unroll
    for (int s = 16; s > 0; s >>= 1) v += __shfl_xor_sync(0xffffffffu, v, s);
    return v;
}
__device__ __forceinline__ float warpmax(float v) {
#pragma unroll
    for (int s = 16; s > 0; s >>= 1) v = fmaxf(v, __shfl_xor_sync(0xffffffffu, v, s));
    return v;
}

__device__ __forceinline__ void waitge(volatile int* f, int tgt) {
    if (*f < tgt) {
        int ns = 16;
        do { __nanosleep(ns); if (ns < 64) ns <<= 1; } while (*f < tgt);
    }
    __threadfence();   // acquire
}
__device__ __forceinline__ void sig(volatile int* f) {
    __threadfence();   // release (caller: after __syncthreads)
    atomicAdd((int*)f, 1);
}

// async 16B copy global->shared
__device__ __forceinline__ void cpa16(void* s, const void* g) {
    unsigned sa = (unsigned)__cvta_generic_to_shared(s);
    asm volatile("cp.async.cg.shared.global [%0], [%1], 16;\n" :: "r"(sa), "l"(g));
}
#define CP_COMMIT()   asm volatile("cp.async.commit_group;\n")
#define CP_WAIT_ALL() asm volatile("cp.async.wait_group 0;\n" ::: "memory")

// sum over values held by threads 0..127 (others pass 0); all 256 call
__device__ __forceinline__ float sum128(float v, int tid, float* red) {
    v = warpsum(v);
    int w = tid >> 5;
    if ((tid & 31) == 0 && w < 4) red[w] = v;
    __syncthreads();
    float s = red[0] + red[1] + red[2] + red[3];
    __syncthreads();
    return s;
}

// per-128-thread-half sum
__device__ __forceinline__ float halfsum(float v, int tid, float* red) {
    v = warpsum(v);
    int w = tid >> 5;
    if ((tid & 31) == 0) red[w] = v;
    __syncthreads();
    int base = w & 4;
    float s = red[base] + red[base + 1] + red[base + 2] + red[base + 3];
    __syncthreads();
    return s;
}

// per-half simultaneous 2-value sum (one barrier round)
__device__ __forceinline__ float2 halfsum2(float a, float b, int tid, float* red) {
    a = warpsum(a); b = warpsum(b);
    int w = tid >> 5;
    if ((tid & 31) == 0) { red[w * 2] = a; red[w * 2 + 1] = b; }
    __syncthreads();
    int base = (w & 4) * 2;
    float sa = red[base]     + red[base + 2] + red[base + 4] + red[base + 6];
    float sb = red[base + 1] + red[base + 3] + red[base + 5] + red[base + 7];
    __syncthreads();
    return make_float2(sa, sb);
}

__global__ void __launch_bounds__(T, 2)
fused_kernel(const int* __restrict__ indices, const float* __restrict__ coords,
             const int* __restrict__ bonds,   const float* __restrict__ noise,
             const float* __restrict__ atom_emb,
             const float* __restrict__ ln1g, const float* __restrict__ ln1b,
             const float* __restrict__ Wq,   const float* __restrict__ bq,
             const float* __restrict__ Wkv,  const float* __restrict__ bkv,
             const float* __restrict__ We,   const float* __restrict__ be,
             const float* __restrict__ Wo,   const float* __restrict__ bo,
             const float* __restrict__ Wg1,
             const float* __restrict__ ln2g, const float* __restrict__ ln2b,
             const float* __restrict__ W1,   const float* __restrict__ b1,
             const float* __restrict__ W2,   const float* __restrict__ b2,
             const float* __restrict__ Wg2,
             const float* __restrict__ Wlin, const float* __restrict__ blin,
             float* __restrict__ out) {
    __shared__ float sm[12288];   // 48 KB static
    int bid = blockIdx.x, tid = threadIdx.x;
    int lane = tid & 31, warp = tid >> 5;

    // ---- zero edges (all blocks) ----------------------------------------
    {
        int z0 = bid * 336;
#pragma unroll
        for (int q = 0; q < 2; q++) {
            int idx = z0 + tid + q * 256;
            if (tid + q * 256 < 336 && idx < 98304) g_edges[idx] = 0.f;
        }
    }
    __syncthreads();
    if (tid == 0) sig(&f_ez[0]);

    // ---- setup: node embed + LN1 (blocks 0..255, one row each) ----------
    if (bid < 256) {
        int row = bid, c = tid & 127;
        float val = 0.f;
        if (tid < 128) val = (c < 127) ? atom_emb[indices[row] * 127 + c] : noise[0];
        float mean = sum128(val, tid, sm) * (1.f / 128.f);
        float d = (tid < 128) ? (val - mean) : 0.f;
        float var = sum128(d * d, tid, sm) * (1.f / 128.f);
        if (tid < 128) {
            g_nodes[row * 128 + c] = val;
            g_xn[row * 128 + c] = d * rsqrtf(var + 1e-5f) * ln1g[c] + ln1b[c];
        }
        __syncthreads();
        if (tid == 0) sig(&f_rt[(row >> 5) << 5]);
    }

    // ---- edge scatter (block 295 only) ----------------------------------
    if (bid == 295) {
        if (tid == 0) waitge(&f_ez[0], G);
        __syncthreads();
        int* bnd = (int*)sm;
        int* win = (int*)(sm + 512);
        for (int t = tid; t < 320; t += 256) bnd[t] = bonds[t];
        __syncthreads();
        if (tid < 160) {
            int i = bnd[tid * 2], j = bnd[tid * 2 + 1], w = 1;
            for (int e = tid + 1; e < 160; e++)
                if (bnd[e * 2] == i && bnd[e * 2 + 1] == j) { w = 0; break; }
            win[tid] = w;
        }
        __syncthreads();
        if (tid < 160 && win[tid]) {
            int i = bnd[tid * 2], j = bnd[tid * 2 + 1];
            for (int b = 0; b < 2; b++) {
                const float* cb = coords + b * 384;
                float dx = cb[i*3]-cb[j*3], dy = cb[i*3+1]-cb[j*3+1], dz = cb[i*3+2]-cb[j*3+2];
                float* p = &g_edges[((b * 128 + i) * 128 + j) * 3];
                p[0] = dx; p[1] = dy; p[2] = dz;
            }
        }
        __syncthreads();
        if (tid < 160 && win[tid]) {
            int i = bnd[tid * 2], j = bnd[tid * 2 + 1];
            for (int b = 0; b < 2; b++) {
                const float* cb = coords + b * 384;
                float dx = cb[i*3]-cb[j*3], dy = cb[i*3+1]-cb[j*3+1], dz = cb[i*3+2]-cb[j*3+2];
                float* p = &g_edges[((b * 128 + j) * 128 + i) * 3];
                p[0] = -dx; p[1] = -dy; p[2] = -dz;
            }
        }
        __syncthreads();
        if (tid == 0) sig(&f_edge[0]);
    }

    // ================= LAYER LOOP =========================================
    for (int l = 0; l < 6; l++) {
        int p = l & 1;

        // ---------- QKV GEMM: 192 tiles (8 rt of 32 rows x 24 ct of 64) --
        if (bid >= 103 && bid < 295) {
            int t = 294 - bid;
            int rt = t / 24, ct = t % 24;
            int r0 = rt * 32, b = rt >> 2;
            int cbase = ct * 64;

            float* xs  = sm;            // 4096 f
            float* wsm = sm + 4096;     // 8192 f

            const float* W; int ld, cs0;
            if (cbase < 512) { W = Wq + l * 128 * 512;  ld = 512;  cs0 = cbase; }
            else             { W = Wkv + l * 128 * 1024; ld = 1024; cs0 = cbase - 512; }

            // prefetch weight tile while waiting on the flag (no dependency)
#pragma unroll
            for (int q = 0; q < 8; q++) {
                int f4 = tid + q * 256;
                int k = f4 >> 4, cx = (f4 & 15) * 4;
                cpa16(&wsm[f4 * 4], &W[k * ld + cs0 + cx]);
            }
            CP_COMMIT();

            if (tid == 0) waitge(&f_rt[rt << 5], 32 * (l + 1));
            __syncthreads();
            {   // xs staging via cp.async
                const float* src = g_xn + r0 * 128;
#pragma unroll
                for (int q = 0; q < 4; q++) {
                    int f4 = tid + q * 256;
                    cpa16(&xs[f4 * 4], &src[f4 * 4]);
                }
                CP_COMMIT();
            }
            CP_WAIT_ALL();
            __syncthreads();

            int tx = tid & 15, ty = tid >> 4;
            int c4 = cbase + tx * 4;
            float4 bias;
            if (cbase < 512) {
                bias = *(const float4*)&bq[l * 512 + c4];
            } else {
                int cs = c4 - 512;
                int cc = (cbase < 1024) ? (c4 - 512) : (c4 - 1024);
                float4 bb  = *(const float4*)&bkv[l * 1024 + cs];
                float4 bee = *(const float4*)&be[l * 512 + cc];
                bias.x = bb.x + bee.x; bias.y = bb.y + bee.y;
                bias.z = bb.z + bee.z; bias.w = bb.w + bee.w;
            }
            const float4* ws4 = (const float4*)wsm;
            float acc[2][4];
#pragma unroll
            for (int r = 0; r < 2; r++) { acc[r][0]=0.f; acc[r][1]=0.f; acc[r][2]=0.f; acc[r][3]=0.f; }
            const float* x0p = xs + (ty * 2) * 128;
            const float* x1p = xs + (ty * 2 + 1) * 128;
#pragma unroll 8
            for (int k = 0; k < 128; k++) {
                float4 w4 = ws4[k * 16 + tx];
                float x0 = x0p[k], x1 = x1p[k];
                acc[0][0] += x0 * w4.x; acc[0][1] += x0 * w4.y;
                acc[0][2] += x0 * w4.z; acc[0][3] += x0 * w4.w;
                acc[1][0] += x1 * w4.x; acc[1][1] += x1 * w4.y;
                acc[1][2] += x1 * w4.z; acc[1][3] += x1 * w4.w;
            }
#pragma unroll
            for (int r = 0; r < 2; r++) {
                int row = r0 + ty * 2 + r;
                float4 o;
                o.x = acc[r][0] + bias.x; o.y = acc[r][1] + bias.y;
                o.z = acc[r][2] + bias.z; o.w = acc[r][3] + bias.w;
                if (cbase < 512) {
                    *(float4*)&g_q[p][row * 512 + c4] = o;
                } else if (cbase < 1024) {
                    int j = row & 127, kc = c4 - 512;
                    g_kT[p][(b * 512 + kc    ) * 128 + j] = o.x;
                    g_kT[p][(b * 512 + kc + 1) * 128 + j] = o.y;
                    g_kT[p][(b * 512 + kc + 2) * 128 + j] = o.z;
                    g_kT[p][(b * 512 + kc + 3) * 128 + j] = o.w;
                } else {
                    *(float4*)&g_v[p][row * 512 + (c4 - 1024)] = o;
                }
            }
            __syncthreads();
            if (tid == 0) sig(&f_qkv[(b * 24 + ct) << 5]);
        }

        // ---------- ATTENTION: 256 jobs (b x h x it8), cooperative sim/PV -
        if (bid < 256) {
            const float* We_l = We + l * 3 * 512;
            int b = bid >> 7, h = (bid >> 4) & 7, it = bid & 15;
            // wait only for q + k tiles (+edges); v wait deferred
            if      (tid == 0)  waitge(&f_qkv[(b * 24 + h) << 5],      4 * (l + 1));
            else if (tid == 32) waitge(&f_qkv[(b * 24 + 8 + h) << 5],  4 * (l + 1));
            else if (tid == 96) waitge(&f_edge[0], 1);
            __syncthreads();

            float* tile = sm;           // 8192 f  (kt, then v, then PV partials)
            float* qs   = sm + 8192;    // 512 f
            float* aps  = sm + 8704;    // 1024 f  (raw sim, then probs)
            float* wsh  = sm + 9728;    // 192 f
            int i = it * 8 + warp;

            {   // kT tile + q via cp.async
                const float* ksrc = g_kT[p] + (b * 512 + h * 64) * 128;
#pragma unroll
                for (int t2 = 0; t2 < 8; t2++) {
                    int idx = tid + t2 * 256;
                    cpa16(&tile[idx * 4], &ksrc[idx * 4]);
                }
                if (tid < 128) {
                    const float* qb = g_q[p] + (b * 128 + it * 8) * 512 + h * 64;
                    int i8 = tid >> 4, dq = (tid & 15) * 4;
                    cpa16(&qs[i8 * 64 + dq], &qb[i8 * 512 + dq]);
                }
                CP_COMMIT();
            }
            if (tid < 192) {
                int c = tid / 64, d = tid % 64;
                wsh[tid] = We_l[c * 512 + h * 64 + d];
            }
            // prefetch edges for this warp's row (registers)
            const float* ebp = g_edges + (b * 128 + i) * 384 + lane * 12;
            float4 ea  = *(const float4*)(ebp);
            float4 eb4 = *(const float4*)(ebp + 4);
            float4 ec4 = *(const float4*)(ebp + 8);
            CP_WAIT_ALL();
            __syncthreads();

            // ---- A1: cooperative sim — warp w covers j in [16w,16w+16),
            //          lanes split d into two halves; kT read ONCE per block
            {
                int k16 = lane & 15, dh = lane >> 4;
                int j = (warp << 4) | k16;
                float accs[8];
#pragma unroll
                for (int il = 0; il < 8; il++) accs[il] = 0.f;
#pragma unroll 8
                for (int dd = 0; dd < 32; dd++) {
                    int d = dh * 32 + dd;
                    float kt = tile[d * 128 + j];
#pragma unroll
                    for (int il = 0; il < 8; il++)
                        accs[il] += qs[il * 64 + d] * kt;
                }
#pragma unroll
                for (int il = 0; il < 8; il++) {
                    float sfull = accs[il] + __shfl_xor_sync(0xffffffffu, accs[il], 16);
                    if (dh == 0) aps[il * 128 + j] = sfull;
                }
            }
            __syncthreads();

            // ---- A2: per-warp-row softmax + edge terms (row il = warp) ---
            float ec0, ec1, ec2;
            {
                float q0 = qs[warp * 64 + lane], q1 = qs[warp * 64 + 32 + lane];
                float qe0 = warpsum(q0 * wsh[lane]       + q1 * wsh[32 + lane]);
                float qe1 = warpsum(q0 * wsh[64 + lane]  + q1 * wsh[96 + lane]);
                float qe2 = warpsum(q0 * wsh[128 + lane] + q1 * wsh[160 + lane]);

                float4 sq = *(float4*)&aps[warp * 128 + lane * 4];
                float E0x=ea.x,  E0y=ea.y,  E0z=ea.z;
                float E1x=ea.w,  E1y=eb4.x, E1z=eb4.y;
                float E2x=eb4.z, E2y=eb4.w, E2z=ec4.x;
                float E3x=ec4.y, E3y=ec4.z, E3z=ec4.w;
                float s0 = (sq.x + qe0*E0x + qe1*E0y + qe2*E0z) * 0.125f;
                float s1 = (sq.y + qe0*E1x + qe1*E1y + qe2*E1z) * 0.125f;
                float s2 = (sq.z + qe0*E2x + qe1*E2y + qe2*E2z) * 0.125f;
                float s3 = (sq.w + qe0*E3x + qe1*E3y + qe2*E3z) * 0.125f;
                float mx = warpmax(fmaxf(fmaxf(s0, s1), fmaxf(s2, s3)));
                float p0 = expf(s0 - mx), p1 = expf(s1 - mx), p2 = expf(s2 - mx), p3 = expf(s3 - mx);
                float sum = warpsum(p0 + p1 + p2 + p3);
                float inv = 1.f / sum;
                p0 *= inv; p1 *= inv; p2 *= inv; p3 *= inv;
                *(float4*)&aps[warp * 128 + lane * 4] = make_float4(p0, p1, p2, p3);
                ec0 = warpsum(p0*E0x + p1*E1x + p2*E2x + p3*E3x);
                ec1 = warpsum(p0*E0y + p1*E1y + p2*E2y + p3*E3y);
                ec2 = warpsum(p0*E0z + p1*E1z + p2*E2z + p3*E3z);
            }
            // deferred v wait: overlapped with sim/softmax above
            if (tid == 64) waitge(&f_qkv[(b * 24 + 16 + h) << 5], 4 * (l + 1));
            __syncthreads();
            {   // v tile [j][64] via cp.async
                const float* vb = g_v[p] + (b * 128) * 512 + h * 64;
#pragma unroll
                for (int t2 = 0; t2 < 8; t2++) {
                    int idx = tid + t2 * 256;
                    int j = idx >> 4, dq = (idx & 15) * 4;
                    cpa16(&tile[j * 64 + dq], &vb[j * 512 + dq]);
                }
                CP_COMMIT();
                CP_WAIT_ALL();
            }
            __syncthreads();

            // ---- B: cooperative PV — warp w covers j in [16w,16w+16),
            //         v read ONCE per block; partials overlay dead v tile
            int d0 = lane * 2;
            {
                float2 accv[8];
#pragma unroll
                for (int il = 0; il < 8; il++) accv[il] = make_float2(0.f, 0.f);
#pragma unroll 4
                for (int jj = 0; jj < 16; jj++) {
                    int j = (warp << 4) + jj;
                    float2 vv = *(float2*)&tile[j * 64 + d0];
#pragma unroll
                    for (int il = 0; il < 8; il++) {
                        float a = aps[il * 128 + j];
                        accv[il].x += a * vv.x; accv[il].y += a * vv.y;
                    }
                }
                __syncthreads();   // all v reads done; tile reusable
#pragma unroll
                for (int il = 0; il < 8; il++)
                    *(float2*)&tile[(warp * 8 + il) * 64 + d0] = accv[il];
            }
            __syncthreads();
            {
                float ox = 0.f, oy = 0.f;
#pragma unroll
                for (int w2 = 0; w2 < 8; w2++) {
                    float2 pp = *(float2*)&tile[(w2 * 8 + warp) * 64 + d0];
                    ox += pp.x; oy += pp.y;
                }
                ox += ec0*wsh[d0]   + ec1*wsh[64+d0]   + ec2*wsh[128+d0];
                oy += ec0*wsh[d0+1] + ec1*wsh[64+d0+1] + ec2*wsh[128+d0+1];

                // per-head Wo partial: yP[c] = sum_d o_d * Wo[h*64+d][c]
                const float* WoL = Wo + l * 512 * 128 + (h * 64) * 128;
                float4 acc = make_float4(0.f, 0.f, 0.f, 0.f);
#pragma unroll
                for (int d = 0; d < 64; d++) {
                    float av = __shfl_sync(0xffffffffu, (d & 1) ? oy : ox, d >> 1);
                    float4 w = *(const float4*)&WoL[d * 128 + lane * 4];
                    acc.x += av * w.x; acc.y += av * w.y;
                    acc.z += av * w.z; acc.w += av * w.w;
                }
                *(float4*)&g_attp[(b * 128 + i) * 1024 + h * 128 + lane * 4] = acc;
            }
            __syncthreads();
            if (tid == 0) sig(&f_att[(b * 16 + it) << 5]);
        }

        // ---------- POST: blocks 0..127, TWO rows each --------------------
        if (bid < 128) {
            int r0 = bid * 2;
            {
                int fb = r0 >> 7, fit = (r0 >> 3) & 15;
                if (tid == 0) waitge(&f_att[(fb * 16 + fit) << 5], 8 * (l + 1));
            }
            __syncthreads();

            const float* W1_l = W1 + l * 128 * 512;
            const float* W2_l = W2 + l * 512 * 128;
            float* ps   = sm + 1024;     // 2048
            float* xn2  = sm + 3072;     // 256  (interleaved)
            float* nod  = sm + 3328;     // 256
            float* ffs2 = sm + 3584;     // 1024 (interleaved)
            float* red  = sm + 4608;     // 32
            int tx = tid & 31, ks = tid >> 5;
            int rr = tid >> 7, c = tid & 127, row = r0 + rr;
            {
                const float* ap = g_attp + row * 1024 + c;
                float x = bo[l * 128 + c];
#pragma unroll
                for (int h8 = 0; h8 < 8; h8++) x += ap[h8 * 128];
                float res = g_nodes[row * 128 + c];
                const float* Wg = Wg1 + l * 384;
                float tg = x * Wg[c] + res * Wg[128 + c] + (x - res) * Wg[256 + c];
                float sg = halfsum(tg, tid, red);
                float gte = 1.f / (1.f + expf(-sg));
                float nv = x * gte + res * (1.f - gte);
                nod[rr * 128 + c] = nv;
                float2 mv = halfsum2(nv, nv * nv, tid, red);
                float mean = mv.x * (1.f / 128.f);
                float var = mv.y * (1.f / 128.f) - mean * mean;
                float dd = nv - mean;
                xn2[c * 2 + rr] = dd * rsqrtf(var + 1e-5f) * ln2g[l*128+c] + ln2b[l*128+c];
            }
            __syncthreads();
            {   // FF1 partials (2-way K split x 128 col-quads, both rows)
                int ks2 = tid >> 7, txf = tid & 127;
                int kb = ks2 * 64, cq = txf * 4;
                float4 a0 = make_float4(0.f,0.f,0.f,0.f), a1 = make_float4(0.f,0.f,0.f,0.f);
#pragma unroll 8
                for (int k = 0; k < 64; k++) {
                    float2 a2 = *(float2*)&xn2[(kb + k) * 2];
                    float4 w = *(const float4*)&W1_l[(kb + k) * 512 + cq];
                    a0.x += a2.x*w.x; a0.y += a2.x*w.y; a0.z += a2.x*w.z; a0.w += a2.x*w.w;
                    a1.x += a2.y*w.x; a1.y += a2.y*w.y; a1.z += a2.y*w.z; a1.w += a2.y*w.w;
                }
                *(float4*)&ps[ks2 * 1024 + cq]       = a0;
                *(float4*)&ps[ks2 * 1024 + 512 + cq] = a1;
            }
            __syncthreads();
            {   // combine + GELU (1024 outputs)
#pragma unroll
                for (int q = 0; q < 4; q++) {
                    int idx = tid + q * 256;
                    int r2 = idx >> 9, cc = idx & 511;
                    float z = ps[r2 * 512 + cc] + ps[1024 + r2 * 512 + cc] + b1[l * 512 + cc];
                    ffs2[cc * 2 + r2] = 0.5f * z * (1.f + erff(z * 0.70710678118654752f));
                }
            }
            __syncthreads();
            {   // FF2, both rows share each weight load
                float4 a0 = make_float4(0.f,0.f,0.f,0.f), a1 = make_float4(0.f,0.f,0.f,0.f);
                int kb = ks * 64, cb = tx * 4;
#pragma unroll 8
                for (int k = 0; k < 64; k++) {
                    float2 a2 = *(float2*)&ffs2[(kb + k) * 2];
                    float4 w = *(const float4*)&W2_l[(kb + k) * 128 + cb];
                    a0.x += a2.x*w.x; a0.y += a2.x*w.y; a0.z += a2.x*w.z; a0.w += a2.x*w.w;
                    a1.x += a2.y*w.x; a1.y += a2.y*w.y; a1.z += a2.y*w.z; a1.w += a2.y*w.w;
                }
                *(float4*)&ps[ks * 256 + cb]       = a0;
                *(float4*)&ps[ks * 256 + 128 + cb] = a1;
            }
            __syncthreads();
            {
                float x = 0.f;
#pragma unroll
                for (int s = 0; s < 8; s++) x += ps[s * 256 + rr * 128 + c];
                x += b2[l * 128 + c];
                float res = nod[rr * 128 + c];
                const float* Wg = Wg2 + l * 384;
                float tg = x * Wg[c] + res * Wg[128 + c] + (x - res) * Wg[256 + c];
                float sg = halfsum(tg, tid, red);
                float gte = 1.f / (1.f + expf(-sg));
                float nn = x * gte + res * (1.f - gte);
                g_nodes[row * 128 + c] = nn;
                if (l < 5) {
                    float2 mv = halfsum2(nn, nn * nn, tid, red);
                    float mean = mv.x * (1.f / 128.f);
                    float var = mv.y * (1.f / 128.f) - mean * mean;
                    float dd = nn - mean;
                    g_xn[row * 128 + c] =
                        dd * rsqrtf(var + 1e-5f) * ln1g[(l+1)*128+c] + ln1b[(l+1)*128+c];
                    __syncthreads();
                    if (tid == 0) {
                        __threadfence();
                        atomicAdd((int*)&f_rt[(r0 >> 5) << 5], 2);
                    }
                } else {
                    float pp = nn * Wlin[c];
                    float s = halfsum(pp, tid, red);
                    if (tid == 0)   red[16] = s;
                    if (tid == 128) red[17] = s;
                    __syncthreads();
                    if (tid == 0) g_part[bid] = red[16] + red[17];
                    __syncthreads();
                    if (tid == 0) {
                        __threadfence();
                        int old = atomicAdd(&f_done[0], 1);
                        ((int*)sm)[0] = (old == 127) ? 1 : 0;
                    }
                    __syncthreads();
                    if (((int*)sm)[0]) {
                        __threadfence();
                        float v = (tid < 128) ? g_part[tid] : 0.f;
                        v = warpsum(v);
                        if (lane == 0) red[8 + warp] = v;
                        __syncthreads();
                        if (tid == 0) {
                            float t8 = 0.f;
                            for (int q = 0; q < 8; q++) t8 += red[8 + q];
                            out[0] = t8 + 256.f * blin[0];
                        }
                        if (tid < 8)  f_rt[tid << 5] = 0;
                        if (tid < 48) f_qkv[tid << 5] = 0;
                        if (tid < 32) f_att[tid << 5] = 0;
                        if (tid == 0) { f_ez[0] = 0; f_edge[0] = 0; f_done[0] = 0; }
                    }
                }
            }
        }
    }
}

extern "C" void kernel_launch(void* const* d_in, const int* in_sizes, int n_in,
                              void* d_out, int out_size) {
    fused_kernel<<<G, T>>>(
        (const int*)d_in[0],  (const float*)d_in[1],  (const int*)d_in[2],
        (const float*)d_in[3], (const float*)d_in[4],
        (const float*)d_in[5], (const float*)d_in[6],
        (const float*)d_in[7], (const float*)d_in[8],
        (const float*)d_in[9], (const float*)d_in[10],
        (const float*)d_in[11], (const float*)d_in[12],
        (const float*)d_in[13], (const float*)d_in[14],
        (const float*)d_in[15],
        (const float*)d_in[16], (const float*)d_in[17],
        (const float*)d_in[18], (const float*)d_in[19],
        (const float*)d_in[20], (const float*)d_in[21],
        (const float*)d_in[22],
        (const float*)d_in[23], (const float*)d_in[24],
        (float*)d_out);
}

// round 13
// speedup vs baseline: 1.3184x; 1.3184x over previous
#include <cuda_runtime.h>
#include <math.h>

#define G 296
#define T 256

// ---------------- device scratch ------------------------------------------
__device__ float g_nodes[256 * 128];
__device__ float g_xn   [256 * 128];
__device__ float g_q  [2][256 * 512];
__device__ float g_kT [2][1024 * 128];   // [p][b*512+c][j]
__device__ float g_v  [2][256 * 512];
__device__ float g_attp[256 * 1024];     // per-head Wo partials [row][h][128]
__device__ float g_edges[2 * 128 * 128 * 3];
__device__ float g_part [128];

// dataflow flags — each padded to its own 128B line (index * 32)
__device__ volatile int f_rt [8  * 32];  // rows done per 32-row group: target 32*(l+1)
__device__ volatile int f_qkv[48 * 32];  // per (b, ct64): target 4*(l+1)
__device__ volatile int f_att[32 * 32];  // per (b, it8):  target 8*(l+1)
__device__ volatile int f_ez [32];       // edge zeroing arrivals (G)
__device__ volatile int f_edge[32];      // edge scatter done (1)
__device__ int          f_done[32];      // POST l5 arrivals (128)

__device__ __forceinline__ float warpsum(float v) {
#pragma unroll
    for (int s = 16; s > 0; s >>= 1) v += __shfl_xor_sync(0xffffffffu, v, s);
    return v;
}
__device__ __forceinline__ float warpmax(float v) {
#pragma unroll
    for (int s = 16; s > 0; s >>= 1) v = fmaxf(v, __shfl_xor_sync(0xffffffffu, v, s));
    return v;
}

__device__ __forceinline__ void waitge(volatile int* f, int tgt) {
    if (*f < tgt) {
        int ns = 16;
        do { __nanosleep(ns); if (ns < 64) ns <<= 1; } while (*f < tgt);
    }
    __threadfence();   // acquire
}
__device__ __forceinline__ void sig(volatile int* f) {
    __threadfence();   // release (caller: after __syncthreads)
    atomicAdd((int*)f, 1);
}

// async 16B copy global->shared
__device__ __forceinline__ void cpa16(void* s, const void* g) {
    unsigned sa = (unsigned)__cvta_generic_to_shared(s);
    asm volatile("cp.async.cg.shared.global [%0], [%1], 16;\n" :: "r"(sa), "l"(g));
}
#define CP_COMMIT()   asm volatile("cp.async.commit_group;\n")
#define CP_WAIT_ALL() asm volatile("cp.async.wait_group 0;\n" ::: "memory")

// sum over values held by threads 0..127 (others pass 0); all 256 call
__device__ __forceinline__ float sum128(float v, int tid, float* red) {
    v = warpsum(v);
    int w = tid >> 5;
    if ((tid & 31) == 0 && w < 4) red[w] = v;
    __syncthreads();
    float s = red[0] + red[1] + red[2] + red[3];
    __syncthreads();
    return s;
}

// per-128-thread-half sum
__device__ __forceinline__ float halfsum(float v, int tid, float* red) {
    v = warpsum(v);
    int w = tid >> 5;
    if ((tid & 31) == 0) red[w] = v;
    __syncthreads();
    int base = w & 4;
    float s = red[base] + red[base + 1] + red[base + 2] + red[base + 3];
    __syncthreads();
    return s;
}

__global__ void __launch_bounds__(T, 2)
fused_kernel(const int* __restrict__ indices, const float* __restrict__ coords,
             const int* __restrict__ bonds,   const float* __restrict__ noise,
             const float* __restrict__ atom_emb,
             const float* __restrict__ ln1g, const float* __restrict__ ln1b,
             const float* __restrict__ Wq,   const float* __restrict__ bq,
             const float* __restrict__ Wkv,  const float* __restrict__ bkv,
             const float* __restrict__ We,   const float* __restrict__ be,
             const float* __restrict__ Wo,   const float* __restrict__ bo,
             const float* __restrict__ Wg1,
             const float* __restrict__ ln2g, const float* __restrict__ ln2b,
             const float* __restrict__ W1,   const float* __restrict__ b1,
             const float* __restrict__ W2,   const float* __restrict__ b2,
             const float* __restrict__ Wg2,
             const float* __restrict__ Wlin, const float* __restrict__ blin,
             float* __restrict__ out) {
    __shared__ float sm[12288];   // 48 KB static
    int bid = blockIdx.x, tid = threadIdx.x;
    int lane = tid & 31, warp = tid >> 5;

    // ---- zero edges (all blocks) ----------------------------------------
    {
        int z0 = bid * 336;
#pragma unroll
        for (int q = 0; q < 2; q++) {
            int idx = z0 + tid + q * 256;
            if (tid + q * 256 < 336 && idx < 98304) g_edges[idx] = 0.f;
        }
    }
    __syncthreads();
    if (tid == 0) sig(&f_ez[0]);

    // ---- setup: node embed + LN1 (blocks 0..255, one row each) ----------
    if (bid < 256) {
        int row = bid, c = tid & 127;
        float val = 0.f;
        if (tid < 128) val = (c < 127) ? atom_emb[indices[row] * 127 + c] : noise[0];
        float mean = sum128(val, tid, sm) * (1.f / 128.f);
        float d = (tid < 128) ? (val - mean) : 0.f;
        float var = sum128(d * d, tid, sm) * (1.f / 128.f);
        if (tid < 128) {
            g_nodes[row * 128 + c] = val;
            g_xn[row * 128 + c] = d * rsqrtf(var + 1e-5f) * ln1g[c] + ln1b[c];
        }
        __syncthreads();
        if (tid == 0) sig(&f_rt[(row >> 5) << 5]);
    }

    // ---- edge scatter (block 295 only) ----------------------------------
    if (bid == 295) {
        if (tid == 0) waitge(&f_ez[0], G);
        __syncthreads();
        int* bnd = (int*)sm;
        int* win = (int*)(sm + 512);
        for (int t = tid; t < 320; t += 256) bnd[t] = bonds[t];
        __syncthreads();
        if (tid < 160) {
            int i = bnd[tid * 2], j = bnd[tid * 2 + 1], w = 1;
            for (int e = tid + 1; e < 160; e++)
                if (bnd[e * 2] == i && bnd[e * 2 + 1] == j) { w = 0; break; }
            win[tid] = w;
        }
        __syncthreads();
        if (tid < 160 && win[tid]) {
            int i = bnd[tid * 2], j = bnd[tid * 2 + 1];
            for (int b = 0; b < 2; b++) {
                const float* cb = coords + b * 384;
                float dx = cb[i*3]-cb[j*3], dy = cb[i*3+1]-cb[j*3+1], dz = cb[i*3+2]-cb[j*3+2];
                float* p = &g_edges[((b * 128 + i) * 128 + j) * 3];
                p[0] = dx; p[1] = dy; p[2] = dz;
            }
        }
        __syncthreads();
        if (tid < 160 && win[tid]) {
            int i = bnd[tid * 2], j = bnd[tid * 2 + 1];
            for (int b = 0; b < 2; b++) {
                const float* cb = coords + b * 384;
                float dx = cb[i*3]-cb[j*3], dy = cb[i*3+1]-cb[j*3+1], dz = cb[i*3+2]-cb[j*3+2];
                float* p = &g_edges[((b * 128 + j) * 128 + i) * 3];
                p[0] = -dx; p[1] = -dy; p[2] = -dz;
            }
        }
        __syncthreads();
        if (tid == 0) sig(&f_edge[0]);
    }

    // ---- QKV tile assignment (max 2 roles per block) ---------------------
    // blocks 0-127: 1 tile (t = bid) + ATT;  blocks 128-255: ATT + POST;
    // blocks 256-295: QKV only (16 singles t=128..143, 24 doubles t=144+k & 168+k)
    int qt[2]; int nqt = 0;
    if (bid < 128) {
        qt[nqt++] = bid;
    } else if (bid >= 256) {
        int bq = bid - 256;
        if (bq < 24) { qt[nqt++] = 144 + bq; qt[nqt++] = 168 + bq; }
        else         { qt[nqt++] = 128 + (bq - 24); }
    }

    // ================= LAYER LOOP =========================================
    for (int l = 0; l < 6; l++) {
        int p = l & 1;

        // ---------- QKV GEMM: 192 tiles (8 rt of 32 rows x 24 ct of 64) --
        for (int ti = 0; ti < nqt; ti++) {
            int t = qt[ti];
            int rt = t / 24, ct = t % 24;
            int r0 = rt * 32, b = rt >> 2;
            int cbase = ct * 64;

            float* xs  = sm;            // 4096 f
            float* wsm = sm + 4096;     // 8192 f

            const float* W; int ld, cs0;
            if (cbase < 512) { W = Wq + l * 128 * 512;  ld = 512;  cs0 = cbase; }
            else             { W = Wkv + l * 128 * 1024; ld = 1024; cs0 = cbase - 512; }

            // prefetch weight tile while waiting on the flag (no dependency)
#pragma unroll
            for (int q = 0; q < 8; q++) {
                int f4 = tid + q * 256;
                int k = f4 >> 4, cx = (f4 & 15) * 4;
                cpa16(&wsm[f4 * 4], &W[k * ld + cs0 + cx]);
            }
            CP_COMMIT();

            if (tid == 0) waitge(&f_rt[rt << 5], 32 * (l + 1));
            __syncthreads();
            {   // xs staging via cp.async
                const float* src = g_xn + r0 * 128;
#pragma unroll
                for (int q = 0; q < 4; q++) {
                    int f4 = tid + q * 256;
                    cpa16(&xs[f4 * 4], &src[f4 * 4]);
                }
                CP_COMMIT();
            }
            CP_WAIT_ALL();
            __syncthreads();

            int tx = tid & 15, ty = tid >> 4;
            int c4 = cbase + tx * 4;
            float4 bias;
            if (cbase < 512) {
                bias = *(const float4*)&bq[l * 512 + c4];
            } else {
                int cs = c4 - 512;
                int cc = (cbase < 1024) ? (c4 - 512) : (c4 - 1024);
                float4 bb  = *(const float4*)&bkv[l * 1024 + cs];
                float4 bee = *(const float4*)&be[l * 512 + cc];
                bias.x = bb.x + bee.x; bias.y = bb.y + bee.y;
                bias.z = bb.z + bee.z; bias.w = bb.w + bee.w;
            }
            const float4* ws4 = (const float4*)wsm;
            float acc[2][4];
#pragma unroll
            for (int r = 0; r < 2; r++) { acc[r][0]=0.f; acc[r][1]=0.f; acc[r][2]=0.f; acc[r][3]=0.f; }
            const float* x0p = xs + (ty * 2) * 128;
            const float* x1p = xs + (ty * 2 + 1) * 128;
#pragma unroll 8
            for (int k = 0; k < 128; k++) {
                float4 w4 = ws4[k * 16 + tx];
                float x0 = x0p[k], x1 = x1p[k];
                acc[0][0] += x0 * w4.x; acc[0][1] += x0 * w4.y;
                acc[0][2] += x0 * w4.z; acc[0][3] += x0 * w4.w;
                acc[1][0] += x1 * w4.x; acc[1][1] += x1 * w4.y;
                acc[1][2] += x1 * w4.z; acc[1][3] += x1 * w4.w;
            }
#pragma unroll
            for (int r = 0; r < 2; r++) {
                int row = r0 + ty * 2 + r;
                float4 o;
                o.x = acc[r][0] + bias.x; o.y = acc[r][1] + bias.y;
                o.z = acc[r][2] + bias.z; o.w = acc[r][3] + bias.w;
                if (cbase < 512) {
                    *(float4*)&g_q[p][row * 512 + c4] = o;
                } else if (cbase < 1024) {
                    int j = row & 127, kc = c4 - 512;
                    g_kT[p][(b * 512 + kc    ) * 128 + j] = o.x;
                    g_kT[p][(b * 512 + kc + 1) * 128 + j] = o.y;
                    g_kT[p][(b * 512 + kc + 2) * 128 + j] = o.z;
                    g_kT[p][(b * 512 + kc + 3) * 128 + j] = o.w;
                } else {
                    *(float4*)&g_v[p][row * 512 + (c4 - 1024)] = o;
                }
            }
            __syncthreads();
            if (tid == 0) sig(&f_qkv[(b * 24 + ct) << 5]);
        }

        // ---------- ATTENTION: 256 jobs (b x h x it8) + per-head Wo partial
        if (bid < 256) {
            const float* We_l = We + l * 3 * 512;
            int b = bid >> 7, h = (bid >> 4) & 7, it = bid & 15;
            if      (tid == 0)  waitge(&f_qkv[(b * 24 + h) << 5],      4 * (l + 1));
            else if (tid == 32) waitge(&f_qkv[(b * 24 + 8 + h) << 5],  4 * (l + 1));
            else if (tid == 64) waitge(&f_qkv[(b * 24 + 16 + h) << 5], 4 * (l + 1));
            else if (tid == 96) waitge(&f_edge[0], 1);
            __syncthreads();

            float* tile = sm;           // 8192 f
            float* qs   = sm + 8192;    // 512 f
            float* aps  = sm + 8704;    // 1024 f
            float* wsh  = sm + 9728;    // 192 f
            int i = it * 8 + warp;

            {   // kT tile + q via cp.async
                const float* ksrc = g_kT[p] + (b * 512 + h * 64) * 128;
#pragma unroll
                for (int t2 = 0; t2 < 8; t2++) {
                    int idx = tid + t2 * 256;
                    cpa16(&tile[idx * 4], &ksrc[idx * 4]);
                }
                if (tid < 128) {
                    const float* qb = g_q[p] + (b * 128 + it * 8) * 512 + h * 64;
                    int i8 = tid >> 4, dq = (tid & 15) * 4;
                    cpa16(&qs[i8 * 64 + dq], &qb[i8 * 512 + dq]);
                }
                CP_COMMIT();
            }
            if (tid < 192) {
                int c = tid / 64, d = tid % 64;
                wsh[tid] = We_l[c * 512 + h * 64 + d];
            }
            // prefetch edges for this warp's row (registers)
            const float* ebp = g_edges + (b * 128 + i) * 384 + lane * 12;
            float4 ea  = *(const float4*)(ebp);
            float4 eb4 = *(const float4*)(ebp + 4);
            float4 ec4 = *(const float4*)(ebp + 8);
            CP_WAIT_ALL();
            __syncthreads();

            float ec0, ec1, ec2;
            {
                float q0 = qs[warp * 64 + lane], q1 = qs[warp * 64 + 32 + lane];
                float qe0 = warpsum(q0 * wsh[lane]       + q1 * wsh[32 + lane]);
                float qe1 = warpsum(q0 * wsh[64 + lane]  + q1 * wsh[96 + lane]);
                float qe2 = warpsum(q0 * wsh[128 + lane] + q1 * wsh[160 + lane]);

                float ax = 0.f, ay = 0.f, az = 0.f, aw = 0.f;
#pragma unroll 16
                for (int d = 0; d < 64; d++) {
                    float qv = qs[warp * 64 + d];
                    float4 kt = *(float4*)&tile[d * 128 + lane * 4];
                    ax += qv * kt.x; ay += qv * kt.y; az += qv * kt.z; aw += qv * kt.w;
                }
                float E0x=ea.x,  E0y=ea.y,  E0z=ea.z;
                float E1x=ea.w,  E1y=eb4.x, E1z=eb4.y;
                float E2x=eb4.z, E2y=eb4.w, E2z=ec4.x;
                float E3x=ec4.y, E3y=ec4.z, E3z=ec4.w;
                float s0 = (ax + qe0*E0x + qe1*E0y + qe2*E0z) * 0.125f;
                float s1 = (ay + qe0*E1x + qe1*E1y + qe2*E1z) * 0.125f;
                float s2 = (az + qe0*E2x + qe1*E2y + qe2*E2z) * 0.125f;
                float s3 = (aw + qe0*E3x + qe1*E3y + qe2*E3z) * 0.125f;
                float mx = warpmax(fmaxf(fmaxf(s0, s1), fmaxf(s2, s3)));
                float p0 = expf(s0 - mx), p1 = expf(s1 - mx), p2 = expf(s2 - mx), p3 = expf(s3 - mx);
                float sum = warpsum(p0 + p1 + p2 + p3);
                float inv = 1.f / sum;
                p0 *= inv; p1 *= inv; p2 *= inv; p3 *= inv;
                *(float4*)&aps[warp * 128 + lane * 4] = make_float4(p0, p1, p2, p3);
                ec0 = warpsum(p0*E0x + p1*E1x + p2*E2x + p3*E3x);
                ec1 = warpsum(p0*E0y + p1*E1y + p2*E2y + p3*E3y);
                ec2 = warpsum(p0*E0z + p1*E1z + p2*E2z + p3*E3z);
            }
            __syncthreads();
            {   // v tile [j][64] via cp.async
                const float* vb = g_v[p] + (b * 128) * 512 + h * 64;
#pragma unroll
                for (int t2 = 0; t2 < 8; t2++) {
                    int idx = tid + t2 * 256;
                    int j = idx >> 4, dq = (idx & 15) * 4;
                    cpa16(&tile[j * 64 + dq], &vb[j * 512 + dq]);
                }
                CP_COMMIT();
                CP_WAIT_ALL();
            }
            __syncthreads();
            {
                int d0 = lane * 2;
                float ox = 0.f, oy = 0.f;
#pragma unroll 8
                for (int jc = 0; jc < 32; jc++) {
                    float4 a4 = *(float4*)&aps[warp * 128 + jc * 4];
                    float2 v0 = *(float2*)&tile[(jc * 4 + 0) * 64 + d0];
                    float2 v1 = *(float2*)&tile[(jc * 4 + 1) * 64 + d0];
                    float2 v2 = *(float2*)&tile[(jc * 4 + 2) * 64 + d0];
                    float2 v3 = *(float2*)&tile[(jc * 4 + 3) * 64 + d0];
                    ox += a4.x * v0.x + a4.y * v1.x + a4.z * v2.x + a4.w * v3.x;
                    oy += a4.x * v0.y + a4.y * v1.y + a4.z * v2.y + a4.w * v3.y;
                }
                ox += ec0*wsh[d0]   + ec1*wsh[64+d0]   + ec2*wsh[128+d0];
                oy += ec0*wsh[d0+1] + ec1*wsh[64+d0+1] + ec2*wsh[128+d0+1];

                // per-head Wo partial: yP[c] = sum_d o_d * Wo[h*64+d][c]
                const float* WoL = Wo + l * 512 * 128 + (h * 64) * 128;
                float4 acc = make_float4(0.f, 0.f, 0.f, 0.f);
#pragma unroll
                for (int d = 0; d < 64; d++) {
                    float av = __shfl_sync(0xffffffffu, (d & 1) ? oy : ox, d >> 1);
                    float4 w = *(const float4*)&WoL[d * 128 + lane * 4];
                    acc.x += av * w.x; acc.y += av * w.y;
                    acc.z += av * w.z; acc.w += av * w.w;
                }
                *(float4*)&g_attp[(b * 128 + i) * 1024 + h * 128 + lane * 4] = acc;
            }
            __syncthreads();
            if (tid == 0) sig(&f_att[(b * 16 + it) << 5]);
        }

        // ---------- POST: blocks 128..255, TWO rows each ------------------
        if (bid >= 128 && bid < 256) {
            int r0 = (bid - 128) * 2;
            {
                int fb = r0 >> 7, fit = (r0 >> 3) & 15;
                if (tid == 0) waitge(&f_att[(fb * 16 + fit) << 5], 8 * (l + 1));
            }
            __syncthreads();

            const float* W1_l = W1 + l * 128 * 512;
            const float* W2_l = W2 + l * 512 * 128;
            float* ps   = sm + 1024;     // 2048
            float* xn2  = sm + 3072;     // 256  (interleaved)
            float* nod  = sm + 3328;     // 256
            float* ffs2 = sm + 3584;     // 1024 (interleaved)
            float* red  = sm + 4608;     // 32
            int tx = tid & 31, ks = tid >> 5;
            int rr = tid >> 7, c = tid & 127, row = r0 + rr;
            {
                const float* ap = g_attp + row * 1024 + c;
                float x = bo[l * 128 + c];
#pragma unroll
                for (int h8 = 0; h8 < 8; h8++) x += ap[h8 * 128];
                float res = g_nodes[row * 128 + c];
                const float* Wg = Wg1 + l * 384;
                float tg = x * Wg[c] + res * Wg[128 + c] + (x - res) * Wg[256 + c];
                float sg = halfsum(tg, tid, red);
                float gte = 1.f / (1.f + expf(-sg));
                float nv = x * gte + res * (1.f - gte);
                nod[rr * 128 + c] = nv;
                float mean = halfsum(nv, tid, red) * (1.f / 128.f);
                float dd = nv - mean;
                float var = halfsum(dd * dd, tid, red) * (1.f / 128.f);
                xn2[c * 2 + rr] = dd * rsqrtf(var + 1e-5f) * ln2g[l*128+c] + ln2b[l*128+c];
            }
            __syncthreads();
            {   // FF1 partials (2-way K split x 128 col-quads, both rows)
                int ks2 = tid >> 7, txf = tid & 127;
                int kb = ks2 * 64, cq = txf * 4;
                float4 a0 = make_float4(0.f,0.f,0.f,0.f), a1 = make_float4(0.f,0.f,0.f,0.f);
#pragma unroll 8
                for (int k = 0; k < 64; k++) {
                    float2 a2 = *(float2*)&xn2[(kb + k) * 2];
                    float4 w = *(const float4*)&W1_l[(kb + k) * 512 + cq];
                    a0.x += a2.x*w.x; a0.y += a2.x*w.y; a0.z += a2.x*w.z; a0.w += a2.x*w.w;
                    a1.x += a2.y*w.x; a1.y += a2.y*w.y; a1.z += a2.y*w.z; a1.w += a2.y*w.w;
                }
                *(float4*)&ps[ks2 * 1024 + cq]       = a0;
                *(float4*)&ps[ks2 * 1024 + 512 + cq] = a1;
            }
            __syncthreads();
            {   // combine + GELU (1024 outputs)
#pragma unroll
                for (int q = 0; q < 4; q++) {
                    int idx = tid + q * 256;
                    int r2 = idx >> 9, cc = idx & 511;
                    float z = ps[r2 * 512 + cc] + ps[1024 + r2 * 512 + cc] + b1[l * 512 + cc];
                    ffs2[cc * 2 + r2] = 0.5f * z * (1.f + erff(z * 0.70710678118654752f));
                }
            }
            __syncthreads();
            {   // FF2, both rows share each weight load
                float4 a0 = make_float4(0.f,0.f,0.f,0.f), a1 = make_float4(0.f,0.f,0.f,0.f);
                int kb = ks * 64, cb = tx * 4;
#pragma unroll 8
                for (int k = 0; k < 64; k++) {
                    float2 a2 = *(float2*)&ffs2[(kb + k) * 2];
                    float4 w = *(const float4*)&W2_l[(kb + k) * 128 + cb];
                    a0.x += a2.x*w.x; a0.y += a2.x*w.y; a0.z += a2.x*w.z; a0.w += a2.x*w.w;
                    a1.x += a2.y*w.x; a1.y += a2.y*w.y; a1.z += a2.y*w.z; a1.w += a2.y*w.w;
                }
                *(float4*)&ps[ks * 256 + cb]       = a0;
                *(float4*)&ps[ks * 256 + 128 + cb] = a1;
            }
            __syncthreads();
            {
                float x = 0.f;
#pragma unroll
                for (int s = 0; s < 8; s++) x += ps[s * 256 + rr * 128 + c];
                x += b2[l * 128 + c];
                float res = nod[rr * 128 + c];
                const float* Wg = Wg2 + l * 384;
                float tg = x * Wg[c] + res * Wg[128 + c] + (x - res) * Wg[256 + c];
                float sg = halfsum(tg, tid, red);
                float gte = 1.f / (1.f + expf(-sg));
                float nn = x * gte + res * (1.f - gte);
                g_nodes[row * 128 + c] = nn;
                if (l < 5) {
                    float mean = halfsum(nn, tid, red) * (1.f / 128.f);
                    float dd = nn - mean;
                    float var = halfsum(dd * dd, tid, red) * (1.f / 128.f);
                    g_xn[row * 128 + c] =
                        dd * rsqrtf(var + 1e-5f) * ln1g[(l+1)*128+c] + ln1b[(l+1)*128+c];
                    __syncthreads();
                    if (tid == 0) {
                        __threadfence();
                        atomicAdd((int*)&f_rt[(r0 >> 5) << 5], 2);
                    }
                } else {
                    float pp = nn * Wlin[c];
                    float s = halfsum(pp, tid, red);
                    if (tid == 0)   red[16] = s;
                    if (tid == 128) red[17] = s;
                    __syncthreads();
                    if (tid == 0) g_part[bid - 128] = red[16] + red[17];
                    __syncthreads();
                    // last arrival does the final reduction + flag reset
                    if (tid == 0) {
                        __threadfence();
                        int old = atomicAdd(&f_done[0], 1);
                        ((int*)sm)[0] = (old == 127) ? 1 : 0;
                    }
                    __syncthreads();
                    if (((int*)sm)[0]) {
                        __threadfence();
                        float v = (tid < 128) ? g_part[tid] : 0.f;
                        v = warpsum(v);
                        if (lane == 0) red[8 + warp] = v;
                        __syncthreads();
                        if (tid == 0) {
                            float t8 = 0.f;
                            for (int q = 0; q < 8; q++) t8 += red[8 + q];
                            out[0] = t8 + 256.f * blin[0];
                        }
                        // reset all flags for the next launch
                        if (tid < 8)  f_rt[tid << 5] = 0;
                        if (tid < 48) f_qkv[tid << 5] = 0;
                        if (tid < 32) f_att[tid << 5] = 0;
                        if (tid == 0) { f_ez[0] = 0; f_edge[0] = 0; f_done[0] = 0; }
                    }
                }
            }
        }
    }
}

extern "C" void kernel_launch(void* const* d_in, const int* in_sizes, int n_in,
                              void* d_out, int out_size) {
    fused_kernel<<<G, T>>>(
        (const int*)d_in[0],  (const float*)d_in[1],  (const int*)d_in[2],
        (const float*)d_in[3], (const float*)d_in[4],
        (const float*)d_in[5], (const float*)d_in[6],
        (const float*)d_in[7], (const float*)d_in[8],
        (const float*)d_in[9], (const float*)d_in[10],
        (const float*)d_in[11], (const float*)d_in[12],
        (const float*)d_in[13], (const float*)d_in[14],
        (const float*)d_in[15],
        (const float*)d_in[16], (const float*)d_in[17],
        (const float*)d_in[18], (const float*)d_in[19],
        (const float*)d_in[20], (const float*)d_in[21],
        (const float*)d_in[22],
        (const float*)d_in[23], (const float*)d_in[24],
        (float*)d_out);
}

// round 14
// speedup vs baseline: 1.4344x; 1.0880x over previous
#include <cuda_runtime.h>
#include <math.h>

#define G 296
#define T 256

// ---------------- device scratch ------------------------------------------
__device__ float g_nodes[256 * 128];
__device__ float g_xn   [256 * 128];
__device__ float g_q  [2][256 * 512];
__device__ float g_kT [2][1024 * 128];   // [p][b*512+c][j]
__device__ float g_v  [2][256 * 512];
__device__ float g_attp[256 * 1024];     // per-head Wo partials [row][h][128]
__device__ float g_edges[2 * 128 * 128 * 3];
__device__ float g_part [128];

// dataflow flags — each padded to its own 128B line (index * 32)
__device__ volatile int f_rt [8  * 32];  // rows done per 32-row group: target 32*(l+1)
__device__ volatile int f_qkv[48 * 32];  // per (b, ct64): target 4*(l+1)
__device__ volatile int f_att[32 * 32];  // per (b, it8):  target 8*(l+1)
__device__ volatile int f_ez [32];       // edge zeroing arrivals (G)
__device__ volatile int f_edge[32];      // edge scatter done (1)
__device__ int          f_done[32];      // POST l5 job arrivals (128)
__device__ int          f_exit[32];      // block exit arrivals (G)

// work-stealing ticket counters (one line per layer)
__device__ int g_qctr[6 * 32];
__device__ int g_actr[6 * 32];
__device__ int g_pctr[6 * 32];

__device__ __forceinline__ float warpsum(float v) {
#pragma unroll
    for (int s = 16; s > 0; s >>= 1) v += __shfl_xor_sync(0xffffffffu, v, s);
    return v;
}
__device__ __forceinline__ float warpmax(float v) {
#pragma unroll
    for (int s = 16; s > 0; s >>= 1) v = fmaxf(v, __shfl_xor_sync(0xffffffffu, v, s));
    return v;
}

__device__ __forceinline__ void waitge(volatile int* f, int tgt) {
    if (*f < tgt) {
        int ns = 16;
        do { __nanosleep(ns); if (ns < 64) ns <<= 1; } while (*f < tgt);
    }
    __threadfence();   // acquire
}
__device__ __forceinline__ void sig(volatile int* f) {
    __threadfence();   // release (caller: after __syncthreads)
    atomicAdd((int*)f, 1);
}

// async 16B copy global->shared
__device__ __forceinline__ void cpa16(void* s, const void* g) {
    unsigned sa = (unsigned)__cvta_generic_to_shared(s);
    asm volatile("cp.async.cg.shared.global [%0], [%1], 16;\n" :: "r"(sa), "l"(g));
}
#define CP_COMMIT()   asm volatile("cp.async.commit_group;\n")
#define CP_WAIT_ALL() asm volatile("cp.async.wait_group 0;\n" ::: "memory")

// sum over values held by threads 0..127 (others pass 0); all 256 call
__device__ __forceinline__ float sum128(float v, int tid, float* red) {
    v = warpsum(v);
    int w = tid >> 5;
    if ((tid & 31) == 0 && w < 4) red[w] = v;
    __syncthreads();
    float s = red[0] + red[1] + red[2] + red[3];
    __syncthreads();
    return s;
}

// per-128-thread-half sum
__device__ __forceinline__ float halfsum(float v, int tid, float* red) {
    v = warpsum(v);
    int w = tid >> 5;
    if ((tid & 31) == 0) red[w] = v;
    __syncthreads();
    int base = w & 4;
    float s = red[base] + red[base + 1] + red[base + 2] + red[base + 3];
    __syncthreads();
    return s;
}

__global__ void __launch_bounds__(T, 2)
fused_kernel(const int* __restrict__ indices, const float* __restrict__ coords,
             const int* __restrict__ bonds,   const float* __restrict__ noise,
             const float* __restrict__ atom_emb,
             const float* __restrict__ ln1g, const float* __restrict__ ln1b,
             const float* __restrict__ Wq,   const float* __restrict__ bq,
             const float* __restrict__ Wkv,  const float* __restrict__ bkv,
             const float* __restrict__ We,   const float* __restrict__ be,
             const float* __restrict__ Wo,   const float* __restrict__ bo,
             const float* __restrict__ Wg1,
             const float* __restrict__ ln2g, const float* __restrict__ ln2b,
             const float* __restrict__ W1,   const float* __restrict__ b1,
             const float* __restrict__ W2,   const float* __restrict__ b2,
             const float* __restrict__ Wg2,
             const float* __restrict__ Wlin, const float* __restrict__ blin,
             float* __restrict__ out) {
    __shared__ float sm[12288];   // 48 KB static
    int bid = blockIdx.x, tid = threadIdx.x;
    int lane = tid & 31, warp = tid >> 5;

    // ---- zero edges (all blocks) ----------------------------------------
    {
        int z0 = bid * 336;
#pragma unroll
        for (int q = 0; q < 2; q++) {
            int idx = z0 + tid + q * 256;
            if (tid + q * 256 < 336 && idx < 98304) g_edges[idx] = 0.f;
        }
    }
    __syncthreads();
    if (tid == 0) sig(&f_ez[0]);

    // ---- setup: node embed + LN1 (blocks 0..255, one row each) ----------
    if (bid < 256) {
        int row = bid, c = tid & 127;
        float val = 0.f;
        if (tid < 128) val = (c < 127) ? atom_emb[indices[row] * 127 + c] : noise[0];
        float mean = sum128(val, tid, sm) * (1.f / 128.f);
        float d = (tid < 128) ? (val - mean) : 0.f;
        float var = sum128(d * d, tid, sm) * (1.f / 128.f);
        if (tid < 128) {
            g_nodes[row * 128 + c] = val;
            g_xn[row * 128 + c] = d * rsqrtf(var + 1e-5f) * ln1g[c] + ln1b[c];
        }
        __syncthreads();
        if (tid == 0) sig(&f_rt[(row >> 5) << 5]);
    }

    // ---- edge scatter (block 295 only) ----------------------------------
    if (bid == 295) {
        if (tid == 0) waitge(&f_ez[0], G);
        __syncthreads();
        int* bnd = (int*)sm;
        int* win = (int*)(sm + 512);
        for (int t = tid; t < 320; t += 256) bnd[t] = bonds[t];
        __syncthreads();
        if (tid < 160) {
            int i = bnd[tid * 2], j = bnd[tid * 2 + 1], w = 1;
            for (int e = tid + 1; e < 160; e++)
                if (bnd[e * 2] == i && bnd[e * 2 + 1] == j) { w = 0; break; }
            win[tid] = w;
        }
        __syncthreads();
        if (tid < 160 && win[tid]) {
            int i = bnd[tid * 2], j = bnd[tid * 2 + 1];
            for (int b = 0; b < 2; b++) {
                const float* cb = coords + b * 384;
                float dx = cb[i*3]-cb[j*3], dy = cb[i*3+1]-cb[j*3+1], dz = cb[i*3+2]-cb[j*3+2];
                float* p = &g_edges[((b * 128 + i) * 128 + j) * 3];
                p[0] = dx; p[1] = dy; p[2] = dz;
            }
        }
        __syncthreads();
        if (tid < 160 && win[tid]) {
            int i = bnd[tid * 2], j = bnd[tid * 2 + 1];
            for (int b = 0; b < 2; b++) {
                const float* cb = coords + b * 384;
                float dx = cb[i*3]-cb[j*3], dy = cb[i*3+1]-cb[j*3+1], dz = cb[i*3+2]-cb[j*3+2];
                float* p = &g_edges[((b * 128 + j) * 128 + i) * 3];
                p[0] = -dx; p[1] = -dy; p[2] = -dz;
            }
        }
        __syncthreads();
        if (tid == 0) sig(&f_edge[0]);
    }

    // ================= LAYER LOOP (work-stealing dispatch) ================
    for (int l = 0; l < 6; l++) {
        int p = l & 1;

        // ---------- QKV GEMM: 192 tiles, dynamic ---------------------------
        for (;;) {
            __syncthreads();
            if (tid == 0) ((int*)sm)[0] = atomicAdd(&g_qctr[l * 32], 1);
            __syncthreads();
            int t = ((int*)sm)[0];
            if (t >= 192) break;

            int rt = t / 24, ct = t % 24;
            int r0 = rt * 32, b = rt >> 2;
            int cbase = ct * 64;

            float* xs  = sm;            // 4096 f
            float* wsm = sm + 4096;     // 8192 f

            const float* W; int ld, cs0;
            if (cbase < 512) { W = Wq + l * 128 * 512;  ld = 512;  cs0 = cbase; }
            else             { W = Wkv + l * 128 * 1024; ld = 1024; cs0 = cbase - 512; }

            // prefetch weight tile while waiting on the flag (no dependency)
#pragma unroll
            for (int q = 0; q < 8; q++) {
                int f4 = tid + q * 256;
                int k = f4 >> 4, cx = (f4 & 15) * 4;
                cpa16(&wsm[f4 * 4], &W[k * ld + cs0 + cx]);
            }
            CP_COMMIT();

            if (tid == 0) waitge(&f_rt[rt << 5], 32 * (l + 1));
            __syncthreads();
            {
                const float4* src = (const float4*)(g_xn + r0 * 128);
                float4* dst = (float4*)xs;
#pragma unroll
                for (int q = 0; q < 4; q++) dst[tid + q * 256] = src[tid + q * 256];
            }
            CP_WAIT_ALL();
            __syncthreads();

            int tx = tid & 15, ty = tid >> 4;
            int c4 = cbase + tx * 4;
            float4 bias;
            if (cbase < 512) {
                bias = *(const float4*)&bq[l * 512 + c4];
            } else {
                int cs = c4 - 512;
                int cc = (cbase < 1024) ? (c4 - 512) : (c4 - 1024);
                float4 bb  = *(const float4*)&bkv[l * 1024 + cs];
                float4 bee = *(const float4*)&be[l * 512 + cc];
                bias.x = bb.x + bee.x; bias.y = bb.y + bee.y;
                bias.z = bb.z + bee.z; bias.w = bb.w + bee.w;
            }
            const float4* ws4 = (const float4*)wsm;
            float acc[2][4];
#pragma unroll
            for (int r = 0; r < 2; r++) { acc[r][0]=0.f; acc[r][1]=0.f; acc[r][2]=0.f; acc[r][3]=0.f; }
            const float* x0p = xs + (ty * 2) * 128;
            const float* x1p = xs + (ty * 2 + 1) * 128;
#pragma unroll 8
            for (int k = 0; k < 128; k++) {
                float4 w4 = ws4[k * 16 + tx];
                float x0 = x0p[k], x1 = x1p[k];
                acc[0][0] += x0 * w4.x; acc[0][1] += x0 * w4.y;
                acc[0][2] += x0 * w4.z; acc[0][3] += x0 * w4.w;
                acc[1][0] += x1 * w4.x; acc[1][1] += x1 * w4.y;
                acc[1][2] += x1 * w4.z; acc[1][3] += x1 * w4.w;
            }
#pragma unroll
            for (int r = 0; r < 2; r++) {
                int row = r0 + ty * 2 + r;
                float4 o;
                o.x = acc[r][0] + bias.x; o.y = acc[r][1] + bias.y;
                o.z = acc[r][2] + bias.z; o.w = acc[r][3] + bias.w;
                if (cbase < 512) {
                    *(float4*)&g_q[p][row * 512 + c4] = o;
                } else if (cbase < 1024) {
                    int j = row & 127, kc = c4 - 512;
                    g_kT[p][(b * 512 + kc    ) * 128 + j] = o.x;
                    g_kT[p][(b * 512 + kc + 1) * 128 + j] = o.y;
                    g_kT[p][(b * 512 + kc + 2) * 128 + j] = o.z;
                    g_kT[p][(b * 512 + kc + 3) * 128 + j] = o.w;
                } else {
                    *(float4*)&g_v[p][row * 512 + (c4 - 1024)] = o;
                }
            }
            __syncthreads();
            if (tid == 0) sig(&f_qkv[(b * 24 + ct) << 5]);
        }

        // ---------- ATTENTION: 256 jobs (b x h x it8), dynamic ------------
        for (;;) {
            __syncthreads();
            if (tid == 0) ((int*)sm)[0] = atomicAdd(&g_actr[l * 32], 1);
            __syncthreads();
            int job = ((int*)sm)[0];
            if (job >= 256) break;

            const float* We_l = We + l * 3 * 512;
            int b = job >> 7, h = (job >> 4) & 7, it = job & 15;
            if      (tid == 0)  waitge(&f_qkv[(b * 24 + h) << 5],      4 * (l + 1));
            else if (tid == 32) waitge(&f_qkv[(b * 24 + 8 + h) << 5],  4 * (l + 1));
            else if (tid == 64) waitge(&f_qkv[(b * 24 + 16 + h) << 5], 4 * (l + 1));
            else if (tid == 96) waitge(&f_edge[0], 1);
            __syncthreads();

            float* tile = sm;           // 8192 f
            float* qs   = sm + 8192;    // 512 f
            float* aps  = sm + 8704;    // 1024 f
            float* wsh  = sm + 9728;    // 192 f
            int i = it * 8 + warp;

            {   // kT tile + q via cp.async
                const float* ksrc = g_kT[p] + (b * 512 + h * 64) * 128;
#pragma unroll
                for (int t2 = 0; t2 < 8; t2++) {
                    int idx = tid + t2 * 256;
                    cpa16(&tile[idx * 4], &ksrc[idx * 4]);
                }
                if (tid < 128) {
                    const float* qb = g_q[p] + (b * 128 + it * 8) * 512 + h * 64;
                    int i8 = tid >> 4, dq = (tid & 15) * 4;
                    cpa16(&qs[i8 * 64 + dq], &qb[i8 * 512 + dq]);
                }
                CP_COMMIT();
            }
            if (tid < 192) {
                int c = tid / 64, d = tid % 64;
                wsh[tid] = We_l[c * 512 + h * 64 + d];
            }
            // prefetch edges for this warp's row (registers)
            const float* ebp = g_edges + (b * 128 + i) * 384 + lane * 12;
            float4 ea  = *(const float4*)(ebp);
            float4 eb4 = *(const float4*)(ebp + 4);
            float4 ec4 = *(const float4*)(ebp + 8);
            CP_WAIT_ALL();
            __syncthreads();

            float ec0, ec1, ec2;
            {
                float q0 = qs[warp * 64 + lane], q1 = qs[warp * 64 + 32 + lane];
                float qe0 = warpsum(q0 * wsh[lane]       + q1 * wsh[32 + lane]);
                float qe1 = warpsum(q0 * wsh[64 + lane]  + q1 * wsh[96 + lane]);
                float qe2 = warpsum(q0 * wsh[128 + lane] + q1 * wsh[160 + lane]);

                float ax = 0.f, ay = 0.f, az = 0.f, aw = 0.f;
#pragma unroll 16
                for (int d = 0; d < 64; d++) {
                    float qv = qs[warp * 64 + d];
                    float4 kt = *(float4*)&tile[d * 128 + lane * 4];
                    ax += qv * kt.x; ay += qv * kt.y; az += qv * kt.z; aw += qv * kt.w;
                }
                float E0x=ea.x,  E0y=ea.y,  E0z=ea.z;
                float E1x=ea.w,  E1y=eb4.x, E1z=eb4.y;
                float E2x=eb4.z, E2y=eb4.w, E2z=ec4.x;
                float E3x=ec4.y, E3y=ec4.z, E3z=ec4.w;
                float s0 = (ax + qe0*E0x + qe1*E0y + qe2*E0z) * 0.125f;
                float s1 = (ay + qe0*E1x + qe1*E1y + qe2*E1z) * 0.125f;
                float s2 = (az + qe0*E2x + qe1*E2y + qe2*E2z) * 0.125f;
                float s3 = (aw + qe0*E3x + qe1*E3y + qe2*E3z) * 0.125f;
                float mx = warpmax(fmaxf(fmaxf(s0, s1), fmaxf(s2, s3)));
                float p0 = expf(s0 - mx), p1 = expf(s1 - mx), p2 = expf(s2 - mx), p3 = expf(s3 - mx);
                float sum = warpsum(p0 + p1 + p2 + p3);
                float inv = 1.f / sum;
                p0 *= inv; p1 *= inv; p2 *= inv; p3 *= inv;
                *(float4*)&aps[warp * 128 + lane * 4] = make_float4(p0, p1, p2, p3);
                ec0 = warpsum(p0*E0x + p1*E1x + p2*E2x + p3*E3x);
                ec1 = warpsum(p0*E0y + p1*E1y + p2*E2y + p3*E3y);
                ec2 = warpsum(p0*E0z + p1*E1z + p2*E2z + p3*E3z);
            }
            __syncthreads();
            {   // v tile [j][64] via cp.async
                const float* vb = g_v[p] + (b * 128) * 512 + h * 64;
#pragma unroll
                for (int t2 = 0; t2 < 8; t2++) {
                    int idx = tid + t2 * 256;
                    int j = idx >> 4, dq = (idx & 15) * 4;
                    cpa16(&tile[j * 64 + dq], &vb[j * 512 + dq]);
                }
                CP_COMMIT();
                CP_WAIT_ALL();
            }
            __syncthreads();
            {
                int d0 = lane * 2;
                float ox = 0.f, oy = 0.f;
#pragma unroll 8
                for (int jc = 0; jc < 32; jc++) {
                    float4 a4 = *(float4*)&aps[warp * 128 + jc * 4];
                    float2 v0 = *(float2*)&tile[(jc * 4 + 0) * 64 + d0];
                    float2 v1 = *(float2*)&tile[(jc * 4 + 1) * 64 + d0];
                    float2 v2 = *(float2*)&tile[(jc * 4 + 2) * 64 + d0];
                    float2 v3 = *(float2*)&tile[(jc * 4 + 3) * 64 + d0];
                    ox += a4.x * v0.x + a4.y * v1.x + a4.z * v2.x + a4.w * v3.x;
                    oy += a4.x * v0.y + a4.y * v1.y + a4.z * v2.y + a4.w * v3.y;
                }
                ox += ec0*wsh[d0]   + ec1*wsh[64+d0]   + ec2*wsh[128+d0];
                oy += ec0*wsh[d0+1] + ec1*wsh[64+d0+1] + ec2*wsh[128+d0+1];

                // per-head Wo partial: yP[c] = sum_d o_d * Wo[h*64+d][c]
                const float* WoL = Wo + l * 512 * 128 + (h * 64) * 128;
                float4 acc = make_float4(0.f, 0.f, 0.f, 0.f);
#pragma unroll
                for (int d = 0; d < 64; d++) {
                    float av = __shfl_sync(0xffffffffu, (d & 1) ? oy : ox, d >> 1);
                    float4 w = *(const float4*)&WoL[d * 128 + lane * 4];
                    acc.x += av * w.x; acc.y += av * w.y;
                    acc.z += av * w.z; acc.w += av * w.w;
                }
                *(float4*)&g_attp[(b * 128 + i) * 1024 + h * 128 + lane * 4] = acc;
            }
            __syncthreads();
            if (tid == 0) sig(&f_att[(b * 16 + it) << 5]);
        }

        // ---------- POST: 128 jobs (2 rows each), dynamic -----------------
        for (;;) {
            __syncthreads();
            if (tid == 0) ((int*)sm)[0] = atomicAdd(&g_pctr[l * 32], 1);
            __syncthreads();
            int job = ((int*)sm)[0];
            if (job >= 128) break;

            int r0 = job * 2;
            {
                int fb = r0 >> 7, fit = (r0 >> 3) & 15;
                if (tid == 0) waitge(&f_att[(fb * 16 + fit) << 5], 8 * (l + 1));
            }
            __syncthreads();

            const float* W1_l = W1 + l * 128 * 512;
            const float* W2_l = W2 + l * 512 * 128;
            float* ps   = sm + 1024;     // 2048
            float* xn2  = sm + 3072;     // 256  (interleaved)
            float* nod  = sm + 3328;     // 256
            float* ffs2 = sm + 3584;     // 1024 (interleaved)
            float* red  = sm + 4608;     // 32
            int tx = tid & 31, ks = tid >> 5;
            int rr = tid >> 7, c = tid & 127, row = r0 + rr;
            {
                const float* ap = g_attp + row * 1024 + c;
                float x = bo[l * 128 + c];
#pragma unroll
                for (int h8 = 0; h8 < 8; h8++) x += ap[h8 * 128];
                float res = g_nodes[row * 128 + c];
                const float* Wg = Wg1 + l * 384;
                float tg = x * Wg[c] + res * Wg[128 + c] + (x - res) * Wg[256 + c];
                float sg = halfsum(tg, tid, red);
                float gte = 1.f / (1.f + expf(-sg));
                float nv = x * gte + res * (1.f - gte);
                nod[rr * 128 + c] = nv;
                float mean = halfsum(nv, tid, red) * (1.f / 128.f);
                float dd = nv - mean;
                float var = halfsum(dd * dd, tid, red) * (1.f / 128.f);
                xn2[c * 2 + rr] = dd * rsqrtf(var + 1e-5f) * ln2g[l*128+c] + ln2b[l*128+c];
            }
            __syncthreads();
            {   // FF1 partials (2-way K split x 128 col-quads, both rows)
                int ks2 = tid >> 7, txf = tid & 127;
                int kb = ks2 * 64, cq = txf * 4;
                float4 a0 = make_float4(0.f,0.f,0.f,0.f), a1 = make_float4(0.f,0.f,0.f,0.f);
#pragma unroll 8
                for (int k = 0; k < 64; k++) {
                    float2 a2 = *(float2*)&xn2[(kb + k) * 2];
                    float4 w = *(const float4*)&W1_l[(kb + k) * 512 + cq];
                    a0.x += a2.x*w.x; a0.y += a2.x*w.y; a0.z += a2.x*w.z; a0.w += a2.x*w.w;
                    a1.x += a2.y*w.x; a1.y += a2.y*w.y; a1.z += a2.y*w.z; a1.w += a2.y*w.w;
                }
                *(float4*)&ps[ks2 * 1024 + cq]       = a0;
                *(float4*)&ps[ks2 * 1024 + 512 + cq] = a1;
            }
            __syncthreads();
            {   // combine + GELU (1024 outputs)
#pragma unroll
                for (int q = 0; q < 4; q++) {
                    int idx = tid + q * 256;
                    int r2 = idx >> 9, cc = idx & 511;
                    float z = ps[r2 * 512 + cc] + ps[1024 + r2 * 512 + cc] + b1[l * 512 + cc];
                    ffs2[cc * 2 + r2] = 0.5f * z * (1.f + erff(z * 0.70710678118654752f));
                }
            }
            __syncthreads();
            {   // FF2, both rows share each weight load
                float4 a0 = make_float4(0.f,0.f,0.f,0.f), a1 = make_float4(0.f,0.f,0.f,0.f);
                int kb = ks * 64, cb = tx * 4;
#pragma unroll 8
                for (int k = 0; k < 64; k++) {
                    float2 a2 = *(float2*)&ffs2[(kb + k) * 2];
                    float4 w = *(const float4*)&W2_l[(kb + k) * 128 + cb];
                    a0.x += a2.x*w.x; a0.y += a2.x*w.y; a0.z += a2.x*w.z; a0.w += a2.x*w.w;
                    a1.x += a2.y*w.x; a1.y += a2.y*w.y; a1.z += a2.y*w.z; a1.w += a2.y*w.w;
                }
                *(float4*)&ps[ks * 256 + cb]       = a0;
                *(float4*)&ps[ks * 256 + 128 + cb] = a1;
            }
            __syncthreads();
            {
                float x = 0.f;
#pragma unroll
                for (int s = 0; s < 8; s++) x += ps[s * 256 + rr * 128 + c];
                x += b2[l * 128 + c];
                float res = nod[rr * 128 + c];
                const float* Wg = Wg2 + l * 384;
                float tg = x * Wg[c] + res * Wg[128 + c] + (x - res) * Wg[256 + c];
                float sg = halfsum(tg, tid, red);
                float gte = 1.f / (1.f + expf(-sg));
                float nn = x * gte + res * (1.f - gte);
                g_nodes[row * 128 + c] = nn;
                if (l < 5) {
                    float mean = halfsum(nn, tid, red) * (1.f / 128.f);
                    float dd = nn - mean;
                    float var = halfsum(dd * dd, tid, red) * (1.f / 128.f);
                    g_xn[row * 128 + c] =
                        dd * rsqrtf(var + 1e-5f) * ln1g[(l+1)*128+c] + ln1b[(l+1)*128+c];
                    __syncthreads();
                    if (tid == 0) {
                        __threadfence();
                        atomicAdd((int*)&f_rt[(r0 >> 5) << 5], 2);
                    }
                } else {
                    float pp = nn * Wlin[c];
                    float s = halfsum(pp, tid, red);
                    if (tid == 0)   red[16] = s;
                    if (tid == 128) red[17] = s;
                    __syncthreads();
                    if (tid == 0) g_part[job] = red[16] + red[17];
                    __syncthreads();
                    // last POST-l5 job does the final reduction
                    if (tid == 0) {
                        __threadfence();
                        int old = atomicAdd(&f_done[0], 1);
                        ((int*)sm)[0] = (old == 127) ? 1 : 0;
                    }
                    __syncthreads();
                    if (((int*)sm)[0]) {
                        __threadfence();
                        float v = (tid < 128) ? g_part[tid] : 0.f;
                        v = warpsum(v);
                        if (lane == 0) red[8 + warp] = v;
                        __syncthreads();
                        if (tid == 0) {
                            float t8 = 0.f;
                            for (int q = 0; q < 8; q++) t8 += red[8 + q];
                            out[0] = t8 + 256.f * blin[0];
                        }
                    }
                    __syncthreads();
                }
            }
        }
    }

    // ---- exit barrier: LAST block to finish resets all state -------------
    __syncthreads();
    if (tid == 0) {
        __threadfence();
        int old = atomicAdd(&f_exit[0], 1);
        if (old == G - 1) {
            for (int q = 0; q < 8;  q++) f_rt[q << 5] = 0;
            for (int q = 0; q < 48; q++) f_qkv[q << 5] = 0;
            for (int q = 0; q < 32; q++) f_att[q << 5] = 0;
            for (int q = 0; q < 6;  q++) {
                g_qctr[q * 32] = 0; g_actr[q * 32] = 0; g_pctr[q * 32] = 0;
            }
            f_ez[0] = 0; f_edge[0] = 0; f_done[0] = 0;
            __threadfence();
            f_exit[0] = 0;
        }
    }
}

extern "C" void kernel_launch(void* const* d_in, const int* in_sizes, int n_in,
                              void* d_out, int out_size) {
    fused_kernel<<<G, T>>>(
        (const int*)d_in[0],  (const float*)d_in[1],  (const int*)d_in[2],
        (const float*)d_in[3], (const float*)d_in[4],
        (const float*)d_in[5], (const float*)d_in[6],
        (const float*)d_in[7], (const float*)d_in[8],
        (const float*)d_in[9], (const float*)d_in[10],
        (const float*)d_in[11], (const float*)d_in[12],
        (const float*)d_in[13], (const float*)d_in[14],
        (const float*)d_in[15],
        (const float*)d_in[16], (const float*)d_in[17],
        (const float*)d_in[18], (const float*)d_in[19],
        (const float*)d_in[20], (const float*)d_in[21],
        (const float*)d_in[22],
        (const float*)d_in[23], (const float*)d_in[24],
        (float*)d_out);
}

// round 15
// speedup vs baseline: 1.5000x; 1.0457x over previous
#include <cuda_runtime.h>
#include <math.h>

#define G 296
#define T 256

// ---------------- device scratch ------------------------------------------
__device__ float g_nodes[256 * 128];
__device__ float g_xn   [256 * 128];
__device__ float g_q  [2][256 * 512];
__device__ float g_kT [2][1024 * 128];   // [p][b*512+c][j]
__device__ float g_v  [2][256 * 512];
__device__ float g_attp[256 * 1024];     // per-head Wo partials [row][h][128]
__device__ float g_edges[2 * 128 * 128 * 3];
__device__ float g_part [128];

// dataflow flags — each padded to its own 128B line (index * 32)
__device__ volatile int f_rt [8  * 32];  // rows done per 32-row group: target 32*(l+1)
__device__ volatile int f_qkv[48 * 32];  // per (b, ct64): target 4*(l+1)
__device__ volatile int f_att[32 * 32];  // per (b, it8):  target 8*(l+1)
__device__ volatile int f_ez [32];       // edge zeroing arrivals (G)
__device__ volatile int f_edge[32];      // edge scatter done (1)
__device__ int          f_done[32];      // POST l5 arrivals (128)

__device__ __forceinline__ float warpsum(float v) {
#pragma unroll
    for (int s = 16; s > 0; s >>= 1) v += __shfl_xor_sync(0xffffffffu, v, s);
    return v;
}
__device__ __forceinline__ float warpmax(float v) {
#pragma unroll
    for (int s = 16; s > 0; s >>= 1) v = fmaxf(v, __shfl_xor_sync(0xffffffffu, v, s));
    return v;
}

__device__ __forceinline__ void waitge(volatile int* f, int tgt) {
    if (*f < tgt) {
        int ns = 20;
        do { __nanosleep(ns); if (ns < 256) ns <<= 1; } while (*f < tgt);
    }
    __threadfence();   // acquire
}
__device__ __forceinline__ void sig(volatile int* f) {
    __threadfence();   // release (caller: after __syncthreads)
    atomicAdd((int*)f, 1);
}

// async 16B copy global->shared
__device__ __forceinline__ void cpa16(void* s, const void* g) {
    unsigned sa = (unsigned)__cvta_generic_to_shared(s);
    asm volatile("cp.async.cg.shared.global [%0], [%1], 16;\n" :: "r"(sa), "l"(g));
}
#define CP_COMMIT()   asm volatile("cp.async.commit_group;\n")
#define CP_WAIT_ALL() asm volatile("cp.async.wait_group 0;\n" ::: "memory")

// sum over values held by threads 0..127 (others pass 0); all 256 call
__device__ __forceinline__ float sum128(float v, int tid, float* red) {
    v = warpsum(v);
    int w = tid >> 5;
    if ((tid & 31) == 0 && w < 4) red[w] = v;
    __syncthreads();
    float s = red[0] + red[1] + red[2] + red[3];
    __syncthreads();
    return s;
}

// per-128-thread-half sum
__device__ __forceinline__ float halfsum(float v, int tid, float* red) {
    v = warpsum(v);
    int w = tid >> 5;
    if ((tid & 31) == 0) red[w] = v;
    __syncthreads();
    int base = w & 4;
    float s = red[base] + red[base + 1] + red[base + 2] + red[base + 3];
    __syncthreads();
    return s;
}

__global__ void __launch_bounds__(T, 2)
fused_kernel(const int* __restrict__ indices, const float* __restrict__ coords,
             const int* __restrict__ bonds,   const float* __restrict__ noise,
             const float* __restrict__ atom_emb,
             const float* __restrict__ ln1g, const float* __restrict__ ln1b,
             const float* __restrict__ Wq,   const float* __restrict__ bq,
             const float* __restrict__ Wkv,  const float* __restrict__ bkv,
             const float* __restrict__ We,   const float* __restrict__ be,
             const float* __restrict__ Wo,   const float* __restrict__ bo,
             const float* __restrict__ Wg1,
             const float* __restrict__ ln2g, const float* __restrict__ ln2b,
             const float* __restrict__ W1,   const float* __restrict__ b1,
             const float* __restrict__ W2,   const float* __restrict__ b2,
             const float* __restrict__ Wg2,
             const float* __restrict__ Wlin, const float* __restrict__ blin,
             float* __restrict__ out) {
    __shared__ float sm[12288];   // 48 KB static
    int bid = blockIdx.x, tid = threadIdx.x;
    int lane = tid & 31, warp = tid >> 5;

    // ---- zero edges (all blocks) ----------------------------------------
    {
        int z0 = bid * 336;
#pragma unroll
        for (int q = 0; q < 2; q++) {
            int idx = z0 + tid + q * 256;
            if (tid + q * 256 < 336 && idx < 98304) g_edges[idx] = 0.f;
        }
    }
    __syncthreads();
    if (tid == 0) sig(&f_ez[0]);

    // ---- setup: node embed + LN1 (blocks 0..255, one row each) ----------
    if (bid < 256) {
        int row = bid, c = tid & 127;
        float val = 0.f;
        if (tid < 128) val = (c < 127) ? atom_emb[indices[row] * 127 + c] : noise[0];
        float mean = sum128(val, tid, sm) * (1.f / 128.f);
        float d = (tid < 128) ? (val - mean) : 0.f;
        float var = sum128(d * d, tid, sm) * (1.f / 128.f);
        if (tid < 128) {
            g_nodes[row * 128 + c] = val;
            g_xn[row * 128 + c] = d * rsqrtf(var + 1e-5f) * ln1g[c] + ln1b[c];
        }
        __syncthreads();
        if (tid == 0) sig(&f_rt[(row >> 5) << 5]);
    }

    // ---- edge scatter (block 295 only) ----------------------------------
    if (bid == 295) {
        if (tid == 0) waitge(&f_ez[0], G);
        __syncthreads();
        int* bnd = (int*)sm;
        int* win = (int*)(sm + 512);
        for (int t = tid; t < 320; t += 256) bnd[t] = bonds[t];
        __syncthreads();
        if (tid < 160) {
            int i = bnd[tid * 2], j = bnd[tid * 2 + 1], w = 1;
            for (int e = tid + 1; e < 160; e++)
                if (bnd[e * 2] == i && bnd[e * 2 + 1] == j) { w = 0; break; }
            win[tid] = w;
        }
        __syncthreads();
        if (tid < 160 && win[tid]) {
            int i = bnd[tid * 2], j = bnd[tid * 2 + 1];
            for (int b = 0; b < 2; b++) {
                const float* cb = coords + b * 384;
                float dx = cb[i*3]-cb[j*3], dy = cb[i*3+1]-cb[j*3+1], dz = cb[i*3+2]-cb[j*3+2];
                float* p = &g_edges[((b * 128 + i) * 128 + j) * 3];
                p[0] = dx; p[1] = dy; p[2] = dz;
            }
        }
        __syncthreads();
        if (tid < 160 && win[tid]) {
            int i = bnd[tid * 2], j = bnd[tid * 2 + 1];
            for (int b = 0; b < 2; b++) {
                const float* cb = coords + b * 384;
                float dx = cb[i*3]-cb[j*3], dy = cb[i*3+1]-cb[j*3+1], dz = cb[i*3+2]-cb[j*3+2];
                float* p = &g_edges[((b * 128 + j) * 128 + i) * 3];
                p[0] = -dx; p[1] = -dy; p[2] = -dz;
            }
        }
        __syncthreads();
        if (tid == 0) sig(&f_edge[0]);
    }

    // ================= LAYER LOOP =========================================
    for (int l = 0; l < 6; l++) {
        int p = l & 1;

        // ---------- QKV GEMM: 192 tiles (8 rt of 32 rows x 24 ct of 64) --
        if (bid >= 103 && bid < 295) {
            int t = 294 - bid;
            int rt = t / 24, ct = t % 24;
            int r0 = rt * 32, b = rt >> 2;
            int cbase = ct * 64;

            float* xs  = sm;            // 4096 f
            float* wsm = sm + 4096;     // 8192 f

            const float* W; int ld, cs0;
            if (cbase < 512) { W = Wq + l * 128 * 512;  ld = 512;  cs0 = cbase; }
            else             { W = Wkv + l * 128 * 1024; ld = 1024; cs0 = cbase - 512; }

            // prefetch weight tile while waiting on the flag (no dependency)
#pragma unroll
            for (int q = 0; q < 8; q++) {
                int f4 = tid + q * 256;
                int k = f4 >> 4, cx = (f4 & 15) * 4;
                cpa16(&wsm[f4 * 4], &W[k * ld + cs0 + cx]);
            }
            CP_COMMIT();

            if (tid == 0) waitge(&f_rt[rt << 5], 32 * (l + 1));
            __syncthreads();
            {
                const float4* src = (const float4*)(g_xn + r0 * 128);
                float4* dst = (float4*)xs;
#pragma unroll
                for (int q = 0; q < 4; q++) dst[tid + q * 256] = src[tid + q * 256];
            }
            CP_WAIT_ALL();
            __syncthreads();

            int tx = tid & 15, ty = tid >> 4;
            int c4 = cbase + tx * 4;
            float4 bias;
            if (cbase < 512) {
                bias = *(const float4*)&bq[l * 512 + c4];
            } else {
                int cs = c4 - 512;
                int cc = (cbase < 1024) ? (c4 - 512) : (c4 - 1024);
                float4 bb  = *(const float4*)&bkv[l * 1024 + cs];
                float4 bee = *(const float4*)&be[l * 512 + cc];
                bias.x = bb.x + bee.x; bias.y = bb.y + bee.y;
                bias.z = bb.z + bee.z; bias.w = bb.w + bee.w;
            }
            const float4* ws4 = (const float4*)wsm;
            float acc[2][4];
#pragma unroll
            for (int r = 0; r < 2; r++) { acc[r][0]=0.f; acc[r][1]=0.f; acc[r][2]=0.f; acc[r][3]=0.f; }
            const float* x0p = xs + (ty * 2) * 128;
            const float* x1p = xs + (ty * 2 + 1) * 128;
#pragma unroll 8
            for (int k = 0; k < 128; k++) {
                float4 w4 = ws4[k * 16 + tx];
                float x0 = x0p[k], x1 = x1p[k];
                acc[0][0] += x0 * w4.x; acc[0][1] += x0 * w4.y;
                acc[0][2] += x0 * w4.z; acc[0][3] += x0 * w4.w;
                acc[1][0] += x1 * w4.x; acc[1][1] += x1 * w4.y;
                acc[1][2] += x1 * w4.z; acc[1][3] += x1 * w4.w;
            }
#pragma unroll
            for (int r = 0; r < 2; r++) {
                int row = r0 + ty * 2 + r;
                float4 o;
                o.x = acc[r][0] + bias.x; o.y = acc[r][1] + bias.y;
                o.z = acc[r][2] + bias.z; o.w = acc[r][3] + bias.w;
                if (cbase < 512) {
                    *(float4*)&g_q[p][row * 512 + c4] = o;
                } else if (cbase < 1024) {
                    int j = row & 127, kc = c4 - 512;
                    g_kT[p][(b * 512 + kc    ) * 128 + j] = o.x;
                    g_kT[p][(b * 512 + kc + 1) * 128 + j] = o.y;
                    g_kT[p][(b * 512 + kc + 2) * 128 + j] = o.z;
                    g_kT[p][(b * 512 + kc + 3) * 128 + j] = o.w;
                } else {
                    *(float4*)&g_v[p][row * 512 + (c4 - 1024)] = o;
                }
            }
            __syncthreads();
            if (tid == 0) sig(&f_qkv[(b * 24 + ct) << 5]);
        }

        // ---------- ATTENTION: 256 jobs (b x h x it8) + per-head Wo partial
        if (bid < 256) {
            const float* We_l = We + l * 3 * 512;
            int b = bid >> 7, h = (bid >> 4) & 7, it = bid & 15;
            // wait for q + k producers (+edges); v wait deferred past softmax
            if      (tid == 0)  waitge(&f_qkv[(b * 24 + h) << 5],      4 * (l + 1));
            else if (tid == 32) waitge(&f_qkv[(b * 24 + 8 + h) << 5],  4 * (l + 1));
            else if (tid == 96) waitge(&f_edge[0], 1);
            __syncthreads();

            float* tile = sm;           // 8192 f
            float* qs   = sm + 8192;    // 512 f
            float* aps  = sm + 8704;    // 1024 f
            float* wsh  = sm + 9728;    // 192 f
            int i = it * 8 + warp;

            {   // kT tile + q via cp.async
                const float* ksrc = g_kT[p] + (b * 512 + h * 64) * 128;
#pragma unroll
                for (int t2 = 0; t2 < 8; t2++) {
                    int idx = tid + t2 * 256;
                    cpa16(&tile[idx * 4], &ksrc[idx * 4]);
                }
                if (tid < 128) {
                    const float* qb = g_q[p] + (b * 128 + it * 8) * 512 + h * 64;
                    int i8 = tid >> 4, dq = (tid & 15) * 4;
                    cpa16(&qs[i8 * 64 + dq], &qb[i8 * 512 + dq]);
                }
                CP_COMMIT();
            }
            if (tid < 192) {
                int c = tid / 64, d = tid % 64;
                wsh[tid] = We_l[c * 512 + h * 64 + d];
            }
            // prefetch edges for this warp's row (registers)
            const float* ebp = g_edges + (b * 128 + i) * 384 + lane * 12;
            float4 ea  = *(const float4*)(ebp);
            float4 eb4 = *(const float4*)(ebp + 4);
            float4 ec4 = *(const float4*)(ebp + 8);
            CP_WAIT_ALL();
            __syncthreads();

            float ec0, ec1, ec2;
            {
                float q0 = qs[warp * 64 + lane], q1 = qs[warp * 64 + 32 + lane];
                float qe0 = warpsum(q0 * wsh[lane]       + q1 * wsh[32 + lane]);
                float qe1 = warpsum(q0 * wsh[64 + lane]  + q1 * wsh[96 + lane]);
                float qe2 = warpsum(q0 * wsh[128 + lane] + q1 * wsh[160 + lane]);

                float ax = 0.f, ay = 0.f, az = 0.f, aw = 0.f;
#pragma unroll 16
                for (int d = 0; d < 64; d++) {
                    float qv = qs[warp * 64 + d];
                    float4 kt = *(float4*)&tile[d * 128 + lane * 4];
                    ax += qv * kt.x; ay += qv * kt.y; az += qv * kt.z; aw += qv * kt.w;
                }
                float E0x=ea.x,  E0y=ea.y,  E0z=ea.z;
                float E1x=ea.w,  E1y=eb4.x, E1z=eb4.y;
                float E2x=eb4.z, E2y=eb4.w, E2z=ec4.x;
                float E3x=ec4.y, E3y=ec4.z, E3z=ec4.w;
                float s0 = (ax + qe0*E0x + qe1*E0y + qe2*E0z) * 0.125f;
                float s1 = (ay + qe0*E1x + qe1*E1y + qe2*E1z) * 0.125f;
                float s2 = (az + qe0*E2x + qe1*E2y + qe2*E2z) * 0.125f;
                float s3 = (aw + qe0*E3x + qe1*E3y + qe2*E3z) * 0.125f;
                float mx = warpmax(fmaxf(fmaxf(s0, s1), fmaxf(s2, s3)));
                float p0 = expf(s0 - mx), p1 = expf(s1 - mx), p2 = expf(s2 - mx), p3 = expf(s3 - mx);
                float sum = warpsum(p0 + p1 + p2 + p3);
                float inv = 1.f / sum;
                p0 *= inv; p1 *= inv; p2 *= inv; p3 *= inv;
                *(float4*)&aps[warp * 128 + lane * 4] = make_float4(p0, p1, p2, p3);
                ec0 = warpsum(p0*E0x + p1*E1x + p2*E2x + p3*E3x);
                ec1 = warpsum(p0*E0y + p1*E1y + p2*E2y + p3*E3y);
                ec2 = warpsum(p0*E0z + p1*E1z + p2*E2z + p3*E3z);
            }
            // deferred v wait: overlapped with the sim/softmax phase above
            if (tid == 64) waitge(&f_qkv[(b * 24 + 16 + h) << 5], 4 * (l + 1));
            __syncthreads();
            {   // v tile [j][64] via cp.async
                const float* vb = g_v[p] + (b * 128) * 512 + h * 64;
#pragma unroll
                for (int t2 = 0; t2 < 8; t2++) {
                    int idx = tid + t2 * 256;
                    int j = idx >> 4, dq = (idx & 15) * 4;
                    cpa16(&tile[j * 64 + dq], &vb[j * 512 + dq]);
                }
                CP_COMMIT();
                CP_WAIT_ALL();
            }
            __syncthreads();
            {
                int d0 = lane * 2;
                float ox = 0.f, oy = 0.f;
#pragma unroll 8
                for (int jc = 0; jc < 32; jc++) {
                    float4 a4 = *(float4*)&aps[warp * 128 + jc * 4];
                    float2 v0 = *(float2*)&tile[(jc * 4 + 0) * 64 + d0];
                    float2 v1 = *(float2*)&tile[(jc * 4 + 1) * 64 + d0];
                    float2 v2 = *(float2*)&tile[(jc * 4 + 2) * 64 + d0];
                    float2 v3 = *(float2*)&tile[(jc * 4 + 3) * 64 + d0];
                    ox += a4.x * v0.x + a4.y * v1.x + a4.z * v2.x + a4.w * v3.x;
                    oy += a4.x * v0.y + a4.y * v1.y + a4.z * v2.y + a4.w * v3.y;
                }
                ox += ec0*wsh[d0]   + ec1*wsh[64+d0]   + ec2*wsh[128+d0];
                oy += ec0*wsh[d0+1] + ec1*wsh[64+d0+1] + ec2*wsh[128+d0+1];

                // per-head Wo partial: yP[c] = sum_d o_d * Wo[h*64+d][c]
                const float* WoL = Wo + l * 512 * 128 + (h * 64) * 128;
                float4 acc = make_float4(0.f, 0.f, 0.f, 0.f);
#pragma unroll
                for (int d = 0; d < 64; d++) {
                    float av = __shfl_sync(0xffffffffu, (d & 1) ? oy : ox, d >> 1);
                    float4 w = *(const float4*)&WoL[d * 128 + lane * 4];
                    acc.x += av * w.x; acc.y += av * w.y;
                    acc.z += av * w.z; acc.w += av * w.w;
                }
                *(float4*)&g_attp[(b * 128 + i) * 1024 + h * 128 + lane * 4] = acc;
            }
            __syncthreads();
            if (tid == 0) sig(&f_att[(b * 16 + it) << 5]);
        }

        // ---------- POST: blocks 0..127, TWO rows each --------------------
        if (bid < 128) {
            int r0 = bid * 2;
            {
                int fb = r0 >> 7, fit = (r0 >> 3) & 15;
                if (tid == 0) waitge(&f_att[(fb * 16 + fit) << 5], 8 * (l + 1));
            }
            __syncthreads();

            const float* W1_l = W1 + l * 128 * 512;
            const float* W2_l = W2 + l * 512 * 128;
            float* ps   = sm + 1024;     // 2048
            float* xn2  = sm + 3072;     // 256  (interleaved)
            float* nod  = sm + 3328;     // 256
            float* ffs2 = sm + 3584;     // 1024 (interleaved)
            float* red  = sm + 4608;     // 32
            int tx = tid & 31, ks = tid >> 5;
            int rr = tid >> 7, c = tid & 127, row = r0 + rr;
            {
                const float* ap = g_attp + row * 1024 + c;
                float x = bo[l * 128 + c];
#pragma unroll
                for (int h8 = 0; h8 < 8; h8++) x += ap[h8 * 128];
                float res = g_nodes[row * 128 + c];
                const float* Wg = Wg1 + l * 384;
                float tg = x * Wg[c] + res * Wg[128 + c] + (x - res) * Wg[256 + c];
                float sg = halfsum(tg, tid, red);
                float gte = 1.f / (1.f + expf(-sg));
                float nv = x * gte + res * (1.f - gte);
                nod[rr * 128 + c] = nv;
                float mean = halfsum(nv, tid, red) * (1.f / 128.f);
                float dd = nv - mean;
                float var = halfsum(dd * dd, tid, red) * (1.f / 128.f);
                xn2[c * 2 + rr] = dd * rsqrtf(var + 1e-5f) * ln2g[l*128+c] + ln2b[l*128+c];
            }
            __syncthreads();
            {   // FF1 partials (2-way K split x 128 col-quads, both rows)
                int ks2 = tid >> 7, txf = tid & 127;
                int kb = ks2 * 64, cq = txf * 4;
                float4 a0 = make_float4(0.f,0.f,0.f,0.f), a1 = make_float4(0.f,0.f,0.f,0.f);
#pragma unroll 8
                for (int k = 0; k < 64; k++) {
                    float2 a2 = *(float2*)&xn2[(kb + k) * 2];
                    float4 w = *(const float4*)&W1_l[(kb + k) * 512 + cq];
                    a0.x += a2.x*w.x; a0.y += a2.x*w.y; a0.z += a2.x*w.z; a0.w += a2.x*w.w;
                    a1.x += a2.y*w.x; a1.y += a2.y*w.y; a1.z += a2.y*w.z; a1.w += a2.y*w.w;
                }
                *(float4*)&ps[ks2 * 1024 + cq]       = a0;
                *(float4*)&ps[ks2 * 1024 + 512 + cq] = a1;
            }
            __syncthreads();
            {   // combine + GELU (1024 outputs)
#pragma unroll
                for (int q = 0; q < 4; q++) {
                    int idx = tid + q * 256;
                    int r2 = idx >> 9, cc = idx & 511;
                    float z = ps[r2 * 512 + cc] + ps[1024 + r2 * 512 + cc] + b1[l * 512 + cc];
                    ffs2[cc * 2 + r2] = 0.5f * z * (1.f + erff(z * 0.70710678118654752f));
                }
            }
            __syncthreads();
            {   // FF2, both rows share each weight load
                float4 a0 = make_float4(0.f,0.f,0.f,0.f), a1 = make_float4(0.f,0.f,0.f,0.f);
                int kb = ks * 64, cb = tx * 4;
#pragma unroll 8
                for (int k = 0; k < 64; k++) {
                    float2 a2 = *(float2*)&ffs2[(kb + k) * 2];
                    float4 w = *(const float4*)&W2_l[(kb + k) * 128 + cb];
                    a0.x += a2.x*w.x; a0.y += a2.x*w.y; a0.z += a2.x*w.z; a0.w += a2.x*w.w;
                    a1.x += a2.y*w.x; a1.y += a2.y*w.y; a1.z += a2.y*w.z; a1.w += a2.y*w.w;
                }
                *(float4*)&ps[ks * 256 + cb]       = a0;
                *(float4*)&ps[ks * 256 + 128 + cb] = a1;
            }
            __syncthreads();
            {
                float x = 0.f;
#pragma unroll
                for (int s = 0; s < 8; s++) x += ps[s * 256 + rr * 128 + c];
                x += b2[l * 128 + c];
                float res = nod[rr * 128 + c];
                const float* Wg = Wg2 + l * 384;
                float tg = x * Wg[c] + res * Wg[128 + c] + (x - res) * Wg[256 + c];
                float sg = halfsum(tg, tid, red);
                float gte = 1.f / (1.f + expf(-sg));
                float nn = x * gte + res * (1.f - gte);
                g_nodes[row * 128 + c] = nn;
                if (l < 5) {
                    float mean = halfsum(nn, tid, red) * (1.f / 128.f);
                    float dd = nn - mean;
                    float var = halfsum(dd * dd, tid, red) * (1.f / 128.f);
                    g_xn[row * 128 + c] =
                        dd * rsqrtf(var + 1e-5f) * ln1g[(l+1)*128+c] + ln1b[(l+1)*128+c];
                    __syncthreads();
                    if (tid == 0) {
                        __threadfence();
                        atomicAdd((int*)&f_rt[(r0 >> 5) << 5], 2);
                    }
                } else {
                    float pp = nn * Wlin[c];
                    float s = halfsum(pp, tid, red);
                    if (tid == 0)   red[16] = s;
                    if (tid == 128) red[17] = s;
                    __syncthreads();
                    if (tid == 0) g_part[bid] = red[16] + red[17];
                    __syncthreads();
                    // last arrival does the final reduction + flag reset
                    if (tid == 0) {
                        __threadfence();
                        int old = atomicAdd(&f_done[0], 1);
                        ((int*)sm)[0] = (old == 127) ? 1 : 0;
                    }
                    __syncthreads();
                    if (((int*)sm)[0]) {
                        __threadfence();
                        float v = (tid < 128) ? g_part[tid] : 0.f;
                        v = warpsum(v);
                        if (lane == 0) red[8 + warp] = v;
                        __syncthreads();
                        if (tid == 0) {
                            float t8 = 0.f;
                            for (int q = 0; q < 8; q++) t8 += red[8 + q];
                            out[0] = t8 + 256.f * blin[0];
                        }
                        // reset all flags for the next launch
                        if (tid < 8)  f_rt[tid << 5] = 0;
                        if (tid < 48) f_qkv[tid << 5] = 0;
                        if (tid < 32) f_att[tid << 5] = 0;
                        if (tid == 0) { f_ez[0] = 0; f_edge[0] = 0; f_done[0] = 0; }
                    }
                }
            }
        }
    }
}

extern "C" void kernel_launch(void* const* d_in, const int* in_sizes, int n_in,
                              void* d_out, int out_size) {
    fused_kernel<<<G, T>>>(
        (const int*)d_in[0],  (const float*)d_in[1],  (const int*)d_in[2],
        (const float*)d_in[3], (const float*)d_in[4],
        (const float*)d_in[5], (const float*)d_in[6],
        (const float*)d_in[7], (const float*)d_in[8],
        (const float*)d_in[9], (const float*)d_in[10],
        (const float*)d_in[11], (const float*)d_in[12],
        (const float*)d_in[13], (const float*)d_in[14],
        (const float*)d_in[15],
        (const float*)d_in[16], (const float*)d_in[17],
        (const float*)d_in[18], (const float*)d_in[19],
        (const float*)d_in[20], (const float*)d_in[21],
        (const float*)d_in[22],
        (const float*)d_in[23], (const float*)d_in[24],
        (float*)d_out);
}

// round 16
// speedup vs baseline: 1.5392x; 1.0261x over previous
#include <cuda_runtime.h>
#include <math.h>

#define G 296
#define T 256

// ---------------- device scratch ------------------------------------------
__device__ float g_nodes[256 * 128];
__device__ float g_xn   [256 * 128];
__device__ float g_q  [2][256 * 512];
__device__ float g_kT [2][1024 * 128];   // [p][b*512+c][j]
__device__ float g_v  [2][256 * 512];
__device__ float g_attp[256 * 1024];     // per-head Wo partials [row][h][128]
__device__ float g_edges[2 * 128 * 128 * 3];
__device__ float g_part [128];

// dataflow flags — each padded to its own 128B line (index * 32)
__device__ volatile int f_rt [8  * 32];  // rows done per 32-row group: target 32*(l+1)
__device__ volatile int f_qkv[48 * 32];  // per (b, ct64): target 4*(l+1)
__device__ volatile int f_att[32 * 32];  // per (b, it8):  target 8*(l+1)
__device__ volatile int f_ez [32];       // edge zeroing arrivals (G)
__device__ volatile int f_edge[32];      // edge scatter done (1)
__device__ int          f_done[32];      // POST l5 arrivals (128)

__device__ __forceinline__ float warpsum(float v) {
#pragma unroll
    for (int s = 16; s > 0; s >>= 1) v += __shfl_xor_sync(0xffffffffu, v, s);
    return v;
}
__device__ __forceinline__ float warpmax(float v) {
#pragma unroll
    for (int s = 16; s > 0; s >>= 1) v = fmaxf(v, __shfl_xor_sync(0xffffffffu, v, s));
    return v;
}

__device__ __forceinline__ void waitge(volatile int* f, int tgt) {
    if (*f < tgt) {
        int ns = 20;
        do { __nanosleep(ns); if (ns < 256) ns <<= 1; } while (*f < tgt);
    }
    __threadfence();   // acquire
}
__device__ __forceinline__ void sig(volatile int* f) {
    __threadfence();   // release (caller: after __syncthreads)
    atomicAdd((int*)f, 1);
}

// async 16B copy global->shared
__device__ __forceinline__ void cpa16(void* s, const void* g) {
    unsigned sa = (unsigned)__cvta_generic_to_shared(s);
    asm volatile("cp.async.cg.shared.global [%0], [%1], 16;\n" :: "r"(sa), "l"(g));
}
#define CP_COMMIT()   asm volatile("cp.async.commit_group;\n")
#define CP_WAIT_ALL() asm volatile("cp.async.wait_group 0;\n" ::: "memory")

// sum over values held by threads 0..127 (others pass 0); all 256 call
__device__ __forceinline__ float sum128(float v, int tid, float* red) {
    v = warpsum(v);
    int w = tid >> 5;
    if ((tid & 31) == 0 && w < 4) red[w] = v;
    __syncthreads();
    float s = red[0] + red[1] + red[2] + red[3];
    __syncthreads();
    return s;
}

// per-128-thread-half sum
__device__ __forceinline__ float halfsum(float v, int tid, float* red) {
    v = warpsum(v);
    int w = tid >> 5;
    if ((tid & 31) == 0) red[w] = v;
    __syncthreads();
    int base = w & 4;
    float s = red[base] + red[base + 1] + red[base + 2] + red[base + 3];
    __syncthreads();
    return s;
}

__global__ void __launch_bounds__(T, 2)
fused_kernel(const int* __restrict__ indices, const float* __restrict__ coords,
             const int* __restrict__ bonds,   const float* __restrict__ noise,
             const float* __restrict__ atom_emb,
             const float* __restrict__ ln1g, const float* __restrict__ ln1b,
             const float* __restrict__ Wq,   const float* __restrict__ bq,
             const float* __restrict__ Wkv,  const float* __restrict__ bkv,
             const float* __restrict__ We,   const float* __restrict__ be,
             const float* __restrict__ Wo,   const float* __restrict__ bo,
             const float* __restrict__ Wg1,
             const float* __restrict__ ln2g, const float* __restrict__ ln2b,
             const float* __restrict__ W1,   const float* __restrict__ b1,
             const float* __restrict__ W2,   const float* __restrict__ b2,
             const float* __restrict__ Wg2,
             const float* __restrict__ Wlin, const float* __restrict__ blin,
             float* __restrict__ out) {
    __shared__ float sm[12288];   // 48 KB static
    int bid = blockIdx.x, tid = threadIdx.x;
    int lane = tid & 31, warp = tid >> 5;

    // ---- zero edges (all blocks) ----------------------------------------
    {
        int z0 = bid * 336;
#pragma unroll
        for (int q = 0; q < 2; q++) {
            int idx = z0 + tid + q * 256;
            if (tid + q * 256 < 336 && idx < 98304) g_edges[idx] = 0.f;
        }
    }
    __syncthreads();
    if (tid == 0) sig(&f_ez[0]);

    // ---- setup: node embed + LN1 (blocks 0..255, one row each) ----------
    if (bid < 256) {
        int row = bid, c = tid & 127;
        float val = 0.f;
        if (tid < 128) val = (c < 127) ? atom_emb[indices[row] * 127 + c] : noise[0];
        float mean = sum128(val, tid, sm) * (1.f / 128.f);
        float d = (tid < 128) ? (val - mean) : 0.f;
        float var = sum128(d * d, tid, sm) * (1.f / 128.f);
        if (tid < 128) {
            g_nodes[row * 128 + c] = val;
            g_xn[row * 128 + c] = d * rsqrtf(var + 1e-5f) * ln1g[c] + ln1b[c];
        }
        __syncthreads();
        if (tid == 0) sig(&f_rt[(row >> 5) << 5]);
    }

    // ---- edge scatter (block 295 only) ----------------------------------
    if (bid == 295) {
        if (tid == 0) waitge(&f_ez[0], G);
        __syncthreads();
        int* bnd = (int*)sm;
        int* win = (int*)(sm + 512);
        for (int t = tid; t < 320; t += 256) bnd[t] = bonds[t];
        __syncthreads();
        if (tid < 160) {
            int i = bnd[tid * 2], j = bnd[tid * 2 + 1], w = 1;
            for (int e = tid + 1; e < 160; e++)
                if (bnd[e * 2] == i && bnd[e * 2 + 1] == j) { w = 0; break; }
            win[tid] = w;
        }
        __syncthreads();
        if (tid < 160 && win[tid]) {
            int i = bnd[tid * 2], j = bnd[tid * 2 + 1];
            for (int b = 0; b < 2; b++) {
                const float* cb = coords + b * 384;
                float dx = cb[i*3]-cb[j*3], dy = cb[i*3+1]-cb[j*3+1], dz = cb[i*3+2]-cb[j*3+2];
                float* p = &g_edges[((b * 128 + i) * 128 + j) * 3];
                p[0] = dx; p[1] = dy; p[2] = dz;
            }
        }
        __syncthreads();
        if (tid < 160 && win[tid]) {
            int i = bnd[tid * 2], j = bnd[tid * 2 + 1];
            for (int b = 0; b < 2; b++) {
                const float* cb = coords + b * 384;
                float dx = cb[i*3]-cb[j*3], dy = cb[i*3+1]-cb[j*3+1], dz = cb[i*3+2]-cb[j*3+2];
                float* p = &g_edges[((b * 128 + j) * 128 + i) * 3];
                p[0] = -dx; p[1] = -dy; p[2] = -dz;
            }
        }
        __syncthreads();
        if (tid == 0) sig(&f_edge[0]);
    }

    // ================= LAYER LOOP =========================================
    for (int l = 0; l < 6; l++) {
        int p = l & 1;

        // ---------- QKV GEMM: 192 tiles (8 rt of 32 rows x 24 ct of 64) --
        if (bid >= 103 && bid < 295) {
            int t = 294 - bid;
            int rt = t / 24, ct = t % 24;
            int r0 = rt * 32, b = rt >> 2;
            int cbase = ct * 64;

            float* xs  = sm;            // 4096 f
            float* wsm = sm + 4096;     // 8192 f

            const float* W; int ld, cs0;
            if (cbase < 512) { W = Wq + l * 128 * 512;  ld = 512;  cs0 = cbase; }
            else             { W = Wkv + l * 128 * 1024; ld = 1024; cs0 = cbase - 512; }

            // prefetch weight tile while waiting on the flag (no dependency)
#pragma unroll
            for (int q = 0; q < 8; q++) {
                int f4 = tid + q * 256;
                int k = f4 >> 4, cx = (f4 & 15) * 4;
                cpa16(&wsm[f4 * 4], &W[k * ld + cs0 + cx]);
            }
            CP_COMMIT();

            if (tid == 0) waitge(&f_rt[rt << 5], 32 * (l + 1));
            __syncthreads();
            {
                const float4* src = (const float4*)(g_xn + r0 * 128);
                float4* dst = (float4*)xs;
#pragma unroll
                for (int q = 0; q < 4; q++) dst[tid + q * 256] = src[tid + q * 256];
            }
            CP_WAIT_ALL();
            __syncthreads();

            int tx = tid & 15, ty = tid >> 4;
            int c4 = cbase + tx * 4;
            float4 bias;
            if (cbase < 512) {
                bias = *(const float4*)&bq[l * 512 + c4];
            } else {
                int cs = c4 - 512;
                int cc = (cbase < 1024) ? (c4 - 512) : (c4 - 1024);
                float4 bb  = *(const float4*)&bkv[l * 1024 + cs];
                float4 bee = *(const float4*)&be[l * 512 + cc];
                bias.x = bb.x + bee.x; bias.y = bb.y + bee.y;
                bias.z = bb.z + bee.z; bias.w = bb.w + bee.w;
            }
            const float4* ws4 = (const float4*)wsm;
            float acc[2][4];
#pragma unroll
            for (int r = 0; r < 2; r++) { acc[r][0]=0.f; acc[r][1]=0.f; acc[r][2]=0.f; acc[r][3]=0.f; }
            const float* x0p = xs + (ty * 2) * 128;
            const float* x1p = xs + (ty * 2 + 1) * 128;
#pragma unroll 8
            for (int k = 0; k < 128; k++) {
                float4 w4 = ws4[k * 16 + tx];
                float x0 = x0p[k], x1 = x1p[k];
                acc[0][0] += x0 * w4.x; acc[0][1] += x0 * w4.y;
                acc[0][2] += x0 * w4.z; acc[0][3] += x0 * w4.w;
                acc[1][0] += x1 * w4.x; acc[1][1] += x1 * w4.y;
                acc[1][2] += x1 * w4.z; acc[1][3] += x1 * w4.w;
            }
#pragma unroll
            for (int r = 0; r < 2; r++) {
                int row = r0 + ty * 2 + r;
                float4 o;
                o.x = acc[r][0] + bias.x; o.y = acc[r][1] + bias.y;
                o.z = acc[r][2] + bias.z; o.w = acc[r][3] + bias.w;
                if (cbase < 512) {
                    *(float4*)&g_q[p][row * 512 + c4] = o;
                } else if (cbase < 1024) {
                    int j = row & 127, kc = c4 - 512;
                    g_kT[p][(b * 512 + kc    ) * 128 + j] = o.x;
                    g_kT[p][(b * 512 + kc + 1) * 128 + j] = o.y;
                    g_kT[p][(b * 512 + kc + 2) * 128 + j] = o.z;
                    g_kT[p][(b * 512 + kc + 3) * 128 + j] = o.w;
                } else {
                    *(float4*)&g_v[p][row * 512 + (c4 - 1024)] = o;
                }
            }
            __syncthreads();
            if (tid == 0) sig(&f_qkv[(b * 24 + ct) << 5]);
        }

        // ---------- ATTENTION: 256 jobs (b x h x it8) + per-head Wo partial
        if (bid < 256) {
            const float* We_l = We + l * 3 * 512;
            int b = bid >> 7, h = (bid >> 4) & 7, it = bid & 15;
            if      (tid == 0)  waitge(&f_qkv[(b * 24 + h) << 5],      4 * (l + 1));
            else if (tid == 32) waitge(&f_qkv[(b * 24 + 8 + h) << 5],  4 * (l + 1));
            else if (tid == 64) waitge(&f_qkv[(b * 24 + 16 + h) << 5], 4 * (l + 1));
            else if (tid == 96) waitge(&f_edge[0], 1);
            __syncthreads();

            float* tile = sm;           // 8192 f
            float* qs   = sm + 8192;    // 512 f
            float* aps  = sm + 8704;    // 1024 f
            float* wsh  = sm + 9728;    // 192 f
            int i = it * 8 + warp;

            {   // kT tile + q via cp.async
                const float* ksrc = g_kT[p] + (b * 512 + h * 64) * 128;
#pragma unroll
                for (int t2 = 0; t2 < 8; t2++) {
                    int idx = tid + t2 * 256;
                    cpa16(&tile[idx * 4], &ksrc[idx * 4]);
                }
                if (tid < 128) {
                    const float* qb = g_q[p] + (b * 128 + it * 8) * 512 + h * 64;
                    int i8 = tid >> 4, dq = (tid & 15) * 4;
                    cpa16(&qs[i8 * 64 + dq], &qb[i8 * 512 + dq]);
                }
                CP_COMMIT();
            }
            if (tid < 192) {
                int c = tid / 64, d = tid % 64;
                wsh[tid] = We_l[c * 512 + h * 64 + d];
            }
            // prefetch edges for this warp's row (registers)
            const float* ebp = g_edges + (b * 128 + i) * 384 + lane * 12;
            float4 ea  = *(const float4*)(ebp);
            float4 eb4 = *(const float4*)(ebp + 4);
            float4 ec4 = *(const float4*)(ebp + 8);
            CP_WAIT_ALL();
            __syncthreads();

            float ec0, ec1, ec2;
            {
                float q0 = qs[warp * 64 + lane], q1 = qs[warp * 64 + 32 + lane];
                float qe0 = warpsum(q0 * wsh[lane]       + q1 * wsh[32 + lane]);
                float qe1 = warpsum(q0 * wsh[64 + lane]  + q1 * wsh[96 + lane]);
                float qe2 = warpsum(q0 * wsh[128 + lane] + q1 * wsh[160 + lane]);

                float ax = 0.f, ay = 0.f, az = 0.f, aw = 0.f;
#pragma unroll 16
                for (int d = 0; d < 64; d++) {
                    float qv = qs[warp * 64 + d];
                    float4 kt = *(float4*)&tile[d * 128 + lane * 4];
                    ax += qv * kt.x; ay += qv * kt.y; az += qv * kt.z; aw += qv * kt.w;
                }
                float E0x=ea.x,  E0y=ea.y,  E0z=ea.z;
                float E1x=ea.w,  E1y=eb4.x, E1z=eb4.y;
                float E2x=eb4.z, E2y=eb4.w, E2z=ec4.x;
                float E3x=ec4.y, E3y=ec4.z, E3z=ec4.w;
                float s0 = (ax + qe0*E0x + qe1*E0y + qe2*E0z) * 0.125f;
                float s1 = (ay + qe0*E1x + qe1*E1y + qe2*E1z) * 0.125f;
                float s2 = (az + qe0*E2x + qe1*E2y + qe2*E2z) * 0.125f;
                float s3 = (aw + qe0*E3x + qe1*E3y + qe2*E3z) * 0.125f;
                float mx = warpmax(fmaxf(fmaxf(s0, s1), fmaxf(s2, s3)));
                float p0 = expf(s0 - mx), p1 = expf(s1 - mx), p2 = expf(s2 - mx), p3 = expf(s3 - mx);
                float sum = warpsum(p0 + p1 + p2 + p3);
                float inv = 1.f / sum;
                p0 *= inv; p1 *= inv; p2 *= inv; p3 *= inv;
                *(float4*)&aps[warp * 128 + lane * 4] = make_float4(p0, p1, p2, p3);
                ec0 = warpsum(p0*E0x + p1*E1x + p2*E2x + p3*E3x);
                ec1 = warpsum(p0*E0y + p1*E1y + p2*E2y + p3*E3y);
                ec2 = warpsum(p0*E0z + p1*E1z + p2*E2z + p3*E3z);
            }
            __syncthreads();
            {   // v tile [j][64] via cp.async
                const float* vb = g_v[p] + (b * 128) * 512 + h * 64;
#pragma unroll
                for (int t2 = 0; t2 < 8; t2++) {
                    int idx = tid + t2 * 256;
                    int j = idx >> 4, dq = (idx & 15) * 4;
                    cpa16(&tile[j * 64 + dq], &vb[j * 512 + dq]);
                }
                CP_COMMIT();
                CP_WAIT_ALL();
            }
            __syncthreads();
            {
                int d0 = lane * 2;
                float ox = 0.f, oy = 0.f;
#pragma unroll 8
                for (int jc = 0; jc < 32; jc++) {
                    float4 a4 = *(float4*)&aps[warp * 128 + jc * 4];
                    float2 v0 = *(float2*)&tile[(jc * 4 + 0) * 64 + d0];
                    float2 v1 = *(float2*)&tile[(jc * 4 + 1) * 64 + d0];
                    float2 v2 = *(float2*)&tile[(jc * 4 + 2) * 64 + d0];
                    float2 v3 = *(float2*)&tile[(jc * 4 + 3) * 64 + d0];
                    ox += a4.x * v0.x + a4.y * v1.x + a4.z * v2.x + a4.w * v3.x;
                    oy += a4.x * v0.y + a4.y * v1.y + a4.z * v2.y + a4.w * v3.y;
                }
                ox += ec0*wsh[d0]   + ec1*wsh[64+d0]   + ec2*wsh[128+d0];
                oy += ec0*wsh[d0+1] + ec1*wsh[64+d0+1] + ec2*wsh[128+d0+1];

                // per-head Wo partial: yP[c] = sum_d o_d * Wo[h*64+d][c]
                const float* WoL = Wo + l * 512 * 128 + (h * 64) * 128;
                float4 acc = make_float4(0.f, 0.f, 0.f, 0.f);
#pragma unroll
                for (int d = 0; d < 64; d++) {
                    float av = __shfl_sync(0xffffffffu, (d & 1) ? oy : ox, d >> 1);
                    float4 w = *(const float4*)&WoL[d * 128 + lane * 4];
                    acc.x += av * w.x; acc.y += av * w.y;
                    acc.z += av * w.z; acc.w += av * w.w;
                }
                *(float4*)&g_attp[(b * 128 + i) * 1024 + h * 128 + lane * 4] = acc;
            }
            __syncthreads();
            if (tid == 0) sig(&f_att[(b * 16 + it) << 5]);
        }

        // ---------- POST: blocks 0..127, TWO rows each --------------------
        if (bid < 128) {
            int r0 = bid * 2;
            {
                int fb = r0 >> 7, fit = (r0 >> 3) & 15;
                if (tid == 0) waitge(&f_att[(fb * 16 + fit) << 5], 8 * (l + 1));
            }
            __syncthreads();

            const float* W1_l = W1 + l * 128 * 512;
            const float* W2_l = W2 + l * 512 * 128;
            float* ps   = sm + 1024;     // 2048
            float* xn2  = sm + 3072;     // 256  (interleaved)
            float* nod  = sm + 3328;     // 256
            float* ffs2 = sm + 3584;     // 1024 (interleaved)
            float* red  = sm + 4608;     // 32
            int tx = tid & 31, ks = tid >> 5;
            int rr = tid >> 7, c = tid & 127, row = r0 + rr;
            {
                const float* ap = g_attp + row * 1024 + c;
                float x = bo[l * 128 + c];
#pragma unroll
                for (int h8 = 0; h8 < 8; h8++) x += ap[h8 * 128];
                float res = g_nodes[row * 128 + c];
                const float* Wg = Wg1 + l * 384;
                float tg = x * Wg[c] + res * Wg[128 + c] + (x - res) * Wg[256 + c];
                float sg = halfsum(tg, tid, red);
                float gte = 1.f / (1.f + expf(-sg));
                float nv = x * gte + res * (1.f - gte);
                nod[rr * 128 + c] = nv;
                float mean = halfsum(nv, tid, red) * (1.f / 128.f);
                float dd = nv - mean;
                float var = halfsum(dd * dd, tid, red) * (1.f / 128.f);
                xn2[c * 2 + rr] = dd * rsqrtf(var + 1e-5f) * ln2g[l*128+c] + ln2b[l*128+c];
            }
            __syncthreads();
            {   // FF1 partials (2-way K split x 128 col-quads, both rows)
                int ks2 = tid >> 7, txf = tid & 127;
                int kb = ks2 * 64, cq = txf * 4;
                float4 a0 = make_float4(0.f,0.f,0.f,0.f), a1 = make_float4(0.f,0.f,0.f,0.f);
#pragma unroll 8
                for (int k = 0; k < 64; k++) {
                    float2 a2 = *(float2*)&xn2[(kb + k) * 2];
                    float4 w = *(const float4*)&W1_l[(kb + k) * 512 + cq];
                    a0.x += a2.x*w.x; a0.y += a2.x*w.y; a0.z += a2.x*w.z; a0.w += a2.x*w.w;
                    a1.x += a2.y*w.x; a1.y += a2.y*w.y; a1.z += a2.y*w.z; a1.w += a2.y*w.w;
                }
                *(float4*)&ps[ks2 * 1024 + cq]       = a0;
                *(float4*)&ps[ks2 * 1024 + 512 + cq] = a1;
            }
            __syncthreads();
            {   // combine + GELU (1024 outputs)
#pragma unroll
                for (int q = 0; q < 4; q++) {
                    int idx = tid + q * 256;
                    int r2 = idx >> 9, cc = idx & 511;
                    float z = ps[r2 * 512 + cc] + ps[1024 + r2 * 512 + cc] + b1[l * 512 + cc];
                    ffs2[cc * 2 + r2] = 0.5f * z * (1.f + erff(z * 0.70710678118654752f));
                }
            }
            __syncthreads();
            {   // FF2, both rows share each weight load
                float4 a0 = make_float4(0.f,0.f,0.f,0.f), a1 = make_float4(0.f,0.f,0.f,0.f);
                int kb = ks * 64, cb = tx * 4;
#pragma unroll 8
                for (int k = 0; k < 64; k++) {
                    float2 a2 = *(float2*)&ffs2[(kb + k) * 2];
                    float4 w = *(const float4*)&W2_l[(kb + k) * 128 + cb];
                    a0.x += a2.x*w.x; a0.y += a2.x*w.y; a0.z += a2.x*w.z; a0.w += a2.x*w.w;
                    a1.x += a2.y*w.x; a1.y += a2.y*w.y; a1.z += a2.y*w.z; a1.w += a2.y*w.w;
                }
                *(float4*)&ps[ks * 256 + cb]       = a0;
                *(float4*)&ps[ks * 256 + 128 + cb] = a1;
            }
            __syncthreads();
            {
                float x = 0.f;
#pragma unroll
                for (int s = 0; s < 8; s++) x += ps[s * 256 + rr * 128 + c];
                x += b2[l * 128 + c];
                float res = nod[rr * 128 + c];
                const float* Wg = Wg2 + l * 384;
                float tg = x * Wg[c] + res * Wg[128 + c] + (x - res) * Wg[256 + c];
                float sg = halfsum(tg, tid, red);
                float gte = 1.f / (1.f + expf(-sg));
                float nn = x * gte + res * (1.f - gte);
                g_nodes[row * 128 + c] = nn;
                if (l < 5) {
                    float mean = halfsum(nn, tid, red) * (1.f / 128.f);
                    float dd = nn - mean;
                    float var = halfsum(dd * dd, tid, red) * (1.f / 128.f);
                    g_xn[row * 128 + c] =
                        dd * rsqrtf(var + 1e-5f) * ln1g[(l+1)*128+c] + ln1b[(l+1)*128+c];
                    __syncthreads();
                    if (tid == 0) {
                        __threadfence();
                        atomicAdd((int*)&f_rt[(r0 >> 5) << 5], 2);
                    }
                } else {
                    float pp = nn * Wlin[c];
                    float s = halfsum(pp, tid, red);
                    if (tid == 0)   red[16] = s;
                    if (tid == 128) red[17] = s;
                    __syncthreads();
                    if (tid == 0) g_part[bid] = red[16] + red[17];
                    __syncthreads();
                    // last arrival does the final reduction + flag reset
                    if (tid == 0) {
                        __threadfence();
                        int old = atomicAdd(&f_done[0], 1);
                        ((int*)sm)[0] = (old == 127) ? 1 : 0;
                    }
                    __syncthreads();
                    if (((int*)sm)[0]) {
                        __threadfence();
                        float v = (tid < 128) ? g_part[tid] : 0.f;
                        v = warpsum(v);
                        if (lane == 0) red[8 + warp] = v;
                        __syncthreads();
                        if (tid == 0) {
                            float t8 = 0.f;
                            for (int q = 0; q < 8; q++) t8 += red[8 + q];
                            out[0] = t8 + 256.f * blin[0];
                        }
                        // reset all flags for the next launch
                        if (tid < 8)  f_rt[tid << 5] = 0;
                        if (tid < 48) f_qkv[tid << 5] = 0;
                        if (tid < 32) f_att[tid << 5] = 0;
                        if (tid == 0) { f_ez[0] = 0; f_edge[0] = 0; f_done[0] = 0; }
                    }
                }
            }
        }
    }
}

extern "C" void kernel_launch(void* const* d_in, const int* in_sizes, int n_in,
                              void* d_out, int out_size) {
    fused_kernel<<<G, T>>>(
        (const int*)d_in[0],  (const float*)d_in[1],  (const int*)d_in[2],
        (const float*)d_in[3], (const float*)d_in[4],
        (const float*)d_in[5], (const float*)d_in[6],
        (const float*)d_in[7], (const float*)d_in[8],
        (const float*)d_in[9], (const float*)d_in[10],
        (const float*)d_in[11], (const float*)d_in[12],
        (const float*)d_in[13], (const float*)d_in[14],
        (const float*)d_in[15],
        (const float*)d_in[16], (const float*)d_in[17],
        (const float*)d_in[18], (const float*)d_in[19],
        (const float*)d_in[20], (const float*)d_in[21],
        (const float*)d_in[22],
        (const float*)d_in[23], (const float*)d_in[24],
        (float*)d_out);
}